// round 6
// baseline (speedup 1.0000x reference)
#include <cuda_runtime.h>
#include <math.h>

#define Bz 32
#define Tz 64
#define Sz 128
#define Hz 512
#define Vz 32000
#define Gz 2048   // 4*H
#define NBLK 128
#define NTHR 256

// ---------------- device scratch ----------------
__device__ __align__(16) float d_x[Tz*Bz*Hz];        // embedded inputs [t][b][h]
__device__ __align__(16) float d_g0ih[Tz*Bz*Gz];     // layer0 ih gates (+both biases)
__device__ __align__(16) float d_h0buf[2*Bz*Hz];     // ping-pong layer0 h
__device__ __align__(16) float d_h1buf[2*Bz*Hz];     // ping-pong layer1 h
__device__ __align__(16) float d_cstate[2*Bz*Hz];    // [l][b][h]
__device__ __align__(16) float d_cat1[Bz*Hz];        // inp1 = h0 + x
__device__ __align__(16) float d_attq[Bz*Hz];        // attention query = h1 + inp1
__device__ __align__(16) float d_outs[Bz*Tz*Hz];     // ctx vectors [b][t][h]
__device__ float d_bias0[Gz];
__device__ float d_bias1[Gz];
__device__ unsigned d_bar_cnt;

__device__ __forceinline__ float sigf(float x) { return 1.f / (1.f + expf(-x)); }

// ---------------- packed f32x2 helpers (sm_103a) ----------------
__device__ __forceinline__ void ffma2(unsigned long long &d,
                                      unsigned long long a,
                                      unsigned long long b)
{
    asm("fma.rn.f32x2 %0, %1, %2, %0;" : "+l"(d) : "l"(a), "l"(b));
}
__device__ __forceinline__ unsigned long long dup2(float x)
{
    unsigned long long r;
    asm("mov.b64 %0, {%1, %1};" : "=l"(r) : "r"(__float_as_uint(x)));
    return r;
}
__device__ __forceinline__ float2 unpack2(unsigned long long v)
{
    unsigned lo, hi;
    asm("mov.b64 {%0, %1}, %2;" : "=r"(lo), "=r"(hi) : "l"(v));
    return make_float2(__uint_as_float(lo), __uint_as_float(hi));
}

// ---------------- grid barrier ----------------
// Writer-side fence only: orders each block's stcg stores before its arrival.
// Readers use __ldcg (L2-direct) for all cross-block data, so no L1
// invalidation (reader fence) is needed; the volatile spin + __syncthreads
// orders the subsequent L2 reads after the release.
__device__ __forceinline__ void gbar(unsigned &nbar)
{
    nbar++;
    __syncthreads();
    if (threadIdx.x == 0) {
        __threadfence();
        atomicAdd(&d_bar_cnt, 1u);
        unsigned target = nbar * (unsigned)NBLK;
        while (*(volatile unsigned*)&d_bar_cnt < target) __nanosleep(32);
    }
    __syncthreads();
}

__global__ void reset_kernel() { d_bar_cnt = 0u; }

// ---------------- prep: bias sums + state init (no weight concat) -------------
__global__ void prep_kernel(const float* __restrict__ bih, const float* __restrict__ bhh,
                            const float* __restrict__ h0, const float* __restrict__ c0)
{
    int i = blockIdx.x * blockDim.x + threadIdx.x;
    if (i < Gz) {
        d_bias0[i] = bih[i] + bhh[i];
        d_bias1[i] = bih[Gz + i] + bhh[Gz + i];
    }
    if (i < Bz*Hz) {
        d_h0buf[i] = h0[i];
        d_h1buf[i] = h0[Bz*Hz + i];
    }
    if (i < 2*Bz*Hz) d_cstate[i] = c0[i];
}

// ---------------- embedding (padding_idx 0; int32/int64 probe) ----------------
__global__ void embed_kernel(const int* __restrict__ ids32, const float* __restrict__ emb)
{
    int i = blockIdx.x * blockDim.x + threadIdx.x;
    if (i >= Tz*Bz*Hz) return;
    bool is64 = (ids32[1] == 0) && (ids32[3] == 0) && (ids32[5] == 0);
    int h = i % Hz;
    int tb = i / Hz;
    int b = tb % Bz;
    int t = tb / Bz;
    int idx = b*Tz + t;
    int id = is64 ? ids32[2*idx] : ids32[idx];
    if (id < 0 || id >= Vz) id = 0;
    d_x[i] = (id == 0) ? 0.f : emb[(size_t)id*Hz + h];
}

// ---------------- GEMM: C[M,N] = A[M,K] * B[N,K]^T (+bias), FFMA2 ----------
// 128x128 tile, BK=16, TM=8, TN=8, 256 threads. LDS:FFMA2 balanced 1:1.
__global__ __launch_bounds__(256)
void gemm_abt(const float* __restrict__ A, const float* __restrict__ Bm,
              const float* __restrict__ bias, float* __restrict__ C,
              int M, int N, int K)
{
    __shared__ __align__(16) float As[16][128];
    __shared__ __align__(16) float Bs[16][128];

    const int m0 = blockIdx.y * 128;
    const int n0 = blockIdx.x * 128;
    const int tid = threadIdx.x;
    const int tx = tid & 15;        // 16 col-groups
    const int ty = tid >> 4;        // 16 row-groups

    // acc2[i2][j]: rows (2*i2, 2*i2+1) x col j — packed f32x2 along M
    unsigned long long acc2[4][8];
#pragma unroll
    for (int i = 0; i < 4; ++i)
#pragma unroll
        for (int j = 0; j < 8; ++j) acc2[i][j] = 0ull;

    const int r0 = tid >> 2;             // rows r0, r0+64 (both A and B tiles)
    const int kq = (tid & 3) * 4;        // k offset

    for (int k0 = 0; k0 < K; k0 += 16) {
        {
            float4 v0 = *(const float4*)&A[(size_t)(m0 + r0)*K + k0 + kq];
            float4 v1 = *(const float4*)&A[(size_t)(m0 + r0 + 64)*K + k0 + kq];
            As[kq+0][r0] = v0.x; As[kq+1][r0] = v0.y;
            As[kq+2][r0] = v0.z; As[kq+3][r0] = v0.w;
            As[kq+0][r0+64] = v1.x; As[kq+1][r0+64] = v1.y;
            As[kq+2][r0+64] = v1.z; As[kq+3][r0+64] = v1.w;
        }
        {
            float4 v0 = *(const float4*)&Bm[(size_t)(n0 + r0)*K + k0 + kq];
            float4 v1 = *(const float4*)&Bm[(size_t)(n0 + r0 + 64)*K + k0 + kq];
            Bs[kq+0][r0] = v0.x; Bs[kq+1][r0] = v0.y;
            Bs[kq+2][r0] = v0.z; Bs[kq+3][r0] = v0.w;
            Bs[kq+0][r0+64] = v1.x; Bs[kq+1][r0+64] = v1.y;
            Bs[kq+2][r0+64] = v1.z; Bs[kq+3][r0+64] = v1.w;
        }
        __syncthreads();
#pragma unroll
        for (int kk = 0; kk < 16; ++kk) {
            ulonglong2 pa = *(const ulonglong2*)&As[kk][ty*8];
            ulonglong2 pb = *(const ulonglong2*)&As[kk][ty*8 + 4];
            unsigned long long ap[4] = { pa.x, pa.y, pb.x, pb.y };
            float4 b0 = *(const float4*)&Bs[kk][tx*8];
            float4 b1 = *(const float4*)&Bs[kk][tx*8 + 4];
            unsigned long long bd[8];
            bd[0] = dup2(b0.x); bd[1] = dup2(b0.y); bd[2] = dup2(b0.z); bd[3] = dup2(b0.w);
            bd[4] = dup2(b1.x); bd[5] = dup2(b1.y); bd[6] = dup2(b1.z); bd[7] = dup2(b1.w);
#pragma unroll
            for (int i2 = 0; i2 < 4; ++i2)
#pragma unroll
                for (int j = 0; j < 8; ++j) ffma2(acc2[i2][j], ap[i2], bd[j]);
        }
        __syncthreads();
    }

    const int n = n0 + tx*8;
    float bv[8];
#pragma unroll
    for (int j = 0; j < 8; ++j) bv[j] = bias ? bias[n + j] : 0.f;
#pragma unroll
    for (int i2 = 0; i2 < 4; ++i2) {
        float2 c[8];
#pragma unroll
        for (int j = 0; j < 8; ++j) c[j] = unpack2(acc2[i2][j]);
        int m = m0 + ty*8 + 2*i2;
        float4 v0a = make_float4(c[0].x + bv[0], c[1].x + bv[1], c[2].x + bv[2], c[3].x + bv[3]);
        float4 v0b = make_float4(c[4].x + bv[4], c[5].x + bv[5], c[6].x + bv[6], c[7].x + bv[7]);
        float4 v1a = make_float4(c[0].y + bv[0], c[1].y + bv[1], c[2].y + bv[2], c[3].y + bv[3]);
        float4 v1b = make_float4(c[4].y + bv[4], c[5].y + bv[5], c[6].y + bv[6], c[7].y + bv[7]);
        *(float4*)&C[(size_t)m*N + n]         = v0a;
        *(float4*)&C[(size_t)m*N + n + 4]     = v0b;
        *(float4*)&C[(size_t)(m+1)*N + n]     = v1a;
        *(float4*)&C[(size_t)(m+1)*N + n + 4] = v1b;
    }
}

// ---------------- persistent scan ----------------
__global__ void __launch_bounds__(NTHR, 1)
scan_kernel(const float* __restrict__ ctx, const float* __restrict__ Whh,
            const float* __restrict__ Wih)
{
    __shared__ __align__(16) float hbuf[8192];   // 32KB: 16 batches x 512
    __shared__ float sg[16][33];
    __shared__ __align__(16) float attq_s[Hz];
    __shared__ float sc_s[Sz];
    __shared__ float s_part[NTHR];
    __shared__ float s_lse;

    const int tid  = threadIdx.x;
    const int lane = tid & 31;
    const int w    = tid >> 5;
    const int blk  = blockIdx.x;
    const int j0   = blk * 4;
    const int cb   = blk >> 2;
    const int cq   = blk & 3;

    const int lr0 = 2*w, lr1 = 2*w + 1;
    const int n0 = (lr0 >> 2)*Hz + j0 + (lr0 & 3);
    const int n1 = (lr1 >> 2)*Hz + j0 + (lr1 & 3);

    // hoist weight rows into registers (loop-invariant)
    float4 aA0[4], aA1[4], aB0[8], aB1[8];
    {
        const float4* W0 = (const float4*)(Whh + (size_t)n0*Hz);
        const float4* W1 = (const float4*)(Whh + (size_t)n1*Hz);
#pragma unroll
        for (int i = 0; i < 4; ++i) { aA0[i] = W0[lane + 32*i]; aA1[i] = W1[lane + 32*i]; }
        const float4* I0 = (const float4*)(Wih + (size_t)(Gz + n0)*Hz);   // Wih layer1
        const float4* I1 = (const float4*)(Wih + (size_t)(Gz + n1)*Hz);
        const float4* H0 = (const float4*)(Whh + (size_t)(Gz + n0)*Hz);   // Whh layer1
        const float4* H1 = (const float4*)(Whh + (size_t)(Gz + n1)*Hz);
#pragma unroll
        for (int i = 0; i < 4; ++i) {
            aB0[i]   = I0[lane + 32*i];  aB1[i]   = I1[lane + 32*i];
            aB0[4+i] = H0[lane + 32*i];  aB1[4+i] = H1[lane + 32*i];
        }
    }

    unsigned nbar = 0;
    float4* hb4 = (float4*)hbuf;

    for (int t = 0; t < Tz; ++t) {
        const int p = t & 1;
        const float* h0p = d_h0buf + p*Bz*Hz;
        float*       h0n = d_h0buf + (p^1)*Bz*Hz;
        const float* h1p = d_h1buf + p*Bz*Hz;
        float*       h1n = d_h1buf + (p^1)*Bz*Hz;

        // ================= Phase A: layer0 gates =================
        {
            const float4* Hp = (const float4*)h0p;
            for (int chunk = 0; chunk < 2; ++chunk) {
#pragma unroll
                for (int idx = tid; idx < 2048; idx += NTHR)
                    hb4[idx] = __ldcg(&Hp[chunk*2048 + idx]);
                __syncthreads();
#pragma unroll 2
                for (int bl = 0; bl < 16; ++bl) {
                    float s0 = 0.f, s1 = 0.f;
                    const float4* hr = hb4 + bl*128;
#pragma unroll
                    for (int i = 0; i < 4; ++i) {
                        float4 h4 = hr[lane + 32*i];
                        s0 += aA0[i].x*h4.x + aA0[i].y*h4.y + aA0[i].z*h4.z + aA0[i].w*h4.w;
                        s1 += aA1[i].x*h4.x + aA1[i].y*h4.y + aA1[i].z*h4.z + aA1[i].w*h4.w;
                    }
#pragma unroll
                    for (int o = 16; o; o >>= 1) {
                        s0 += __shfl_xor_sync(0xffffffffu, s0, o);
                        s1 += __shfl_xor_sync(0xffffffffu, s1, o);
                    }
                    if (lane == 0) { sg[lr0][chunk*16 + bl] = s0; sg[lr1][chunk*16 + bl] = s1; }
                }
                __syncthreads();
            }
            if (tid < 128) {
                int b = tid >> 2, jj = tid & 3;
                int j = j0 + jj;
                const float* seed = d_g0ih + ((size_t)t*Bz + b)*Gz;
                float gi = sg[0  + jj][b] + seed[j];
                float gf = sg[4  + jj][b] + seed[Hz + j];
                float gg = sg[8  + jj][b] + seed[2*Hz + j];
                float go = sg[12 + jj][b] + seed[3*Hz + j];
                int ci = b*Hz + j;
                float c = sigf(gf)*d_cstate[ci] + sigf(gi)*tanhf(gg);
                float h = sigf(go)*tanhf(c);
                d_cstate[ci] = c;
                __stcg(&h0n[ci], h);
                __stcg(&d_cat1[ci], h + d_x[((size_t)t*Bz + b)*Hz + j]);
            }
        }
        gbar(nbar);

        // ================= Phase B: layer1 gates (K=1024) =================
        {
            for (int half = 0; half < 2; ++half) {
                const float4* src = half ? (const float4*)h1p : (const float4*)d_cat1;
                const float4* wr0 = half ? (aB0 + 4) : aB0;
                const float4* wr1 = half ? (aB1 + 4) : aB1;
                for (int chunk = 0; chunk < 2; ++chunk) {
#pragma unroll
                    for (int idx = tid; idx < 2048; idx += NTHR)
                        hb4[idx] = __ldcg(&src[chunk*2048 + idx]);
                    __syncthreads();
#pragma unroll 2
                    for (int bl = 0; bl < 16; ++bl) {
                        float s0 = 0.f, s1 = 0.f;
                        const float4* hr = hb4 + bl*128;
#pragma unroll
                        for (int i = 0; i < 4; ++i) {
                            float4 h4 = hr[lane + 32*i];
                            s0 += wr0[i].x*h4.x + wr0[i].y*h4.y + wr0[i].z*h4.z + wr0[i].w*h4.w;
                            s1 += wr1[i].x*h4.x + wr1[i].y*h4.y + wr1[i].z*h4.z + wr1[i].w*h4.w;
                        }
#pragma unroll
                        for (int o = 16; o; o >>= 1) {
                            s0 += __shfl_xor_sync(0xffffffffu, s0, o);
                            s1 += __shfl_xor_sync(0xffffffffu, s1, o);
                        }
                        if (lane == 0) {
                            int b = chunk*16 + bl;
                            if (half == 0) { sg[lr0][b] = s0; sg[lr1][b] = s1; }
                            else           { sg[lr0][b] += s0; sg[lr1][b] += s1; }
                        }
                    }
                    __syncthreads();
                }
            }
            if (tid < 128) {
                int b = tid >> 2, jj = tid & 3;
                int j = j0 + jj;
                float gi = sg[0  + jj][b] + d_bias1[j];
                float gf = sg[4  + jj][b] + d_bias1[Hz + j];
                float gg = sg[8  + jj][b] + d_bias1[2*Hz + j];
                float go = sg[12 + jj][b] + d_bias1[3*Hz + j];
                int ci = Bz*Hz + b*Hz + j;
                float c = sigf(gf)*d_cstate[ci] + sigf(gi)*tanhf(gg);
                float h = sigf(go)*tanhf(c);
                d_cstate[ci] = c;
                __stcg(&h1n[b*Hz + j], h);
                __stcg(&d_attq[b*Hz + j], h + __ldcg(&d_cat1[b*Hz + j]));
            }
        }
        gbar(nbar);

        // ================= Phase C: attention (no trailing barrier) =============
        {
            for (int i = tid; i < Hz; i += NTHR) attq_s[i] = __ldcg(&d_attq[cb*Hz + i]);
            __syncthreads();

            const float4* A4 = (const float4*)attq_s;
            for (int s = w*16; s < w*16 + 16; ++s) {
                const float4* C4 = (const float4*)(ctx + ((size_t)cb*Sz + s)*Hz);
                float acc = 0.f;
#pragma unroll
                for (int i = 0; i < 4; ++i) {
                    float4 c4 = C4[lane + 32*i];
                    float4 a4 = A4[lane + 32*i];
                    acc += c4.x*a4.x + c4.y*a4.y + c4.z*a4.z + c4.w*a4.w;
                }
#pragma unroll
                for (int o = 16; o; o >>= 1) acc += __shfl_xor_sync(0xffffffffu, acc, o);
                if (lane == 0) sc_s[s] = acc;
            }
            __syncthreads();

            if (w == 0) {
                float m = -1e30f;
                for (int s = lane; s < Sz; s += 32) m = fmaxf(m, sc_s[s]);
#pragma unroll
                for (int o = 16; o; o >>= 1) m = fmaxf(m, __shfl_xor_sync(0xffffffffu, m, o));
                float sm = 0.f;
                for (int s = lane; s < Sz; s += 32) sm += expf(sc_s[s] - m);
#pragma unroll
                for (int o = 16; o; o >>= 1) sm += __shfl_xor_sync(0xffffffffu, sm, o);
                if (lane == 0) s_lse = m + logf(sm);
            }
            __syncthreads();
            float lse = s_lse;

            int h = cq*128 + (tid & 127);
            int sgrp = tid >> 7;
            float acc = 0.f;
            for (int s = sgrp*64; s < sgrp*64 + 64; ++s)
                acc += ctx[((size_t)cb*Sz + s)*Hz + h] * (sc_s[s] - lse);
            s_part[tid] = acc;
            __syncthreads();
            if (tid < 128)
                d_outs[((size_t)cb*Tz + t)*Hz + h] = s_part[tid] + s_part[tid + 128];
            __syncthreads();
        }
    }
}

// ---------------- tail: hT, cT ----------------
__global__ void tail_kernel(float* __restrict__ out)
{
    int i = blockIdx.x * blockDim.x + threadIdx.x;
    const size_t base = (size_t)Bz*Tz*Vz;
    if (i < Bz*Hz)                 out[base + i] = d_h0buf[i];       // T even -> buf 0
    else if (i < 2*Bz*Hz)          out[base + i] = d_h1buf[i - Bz*Hz];
    else if (i < 4*Bz*Hz)          out[base + i] = d_cstate[i - 2*Bz*Hz];
}

// ---------------- launch ----------------
extern "C" void kernel_launch(void* const* d_in, const int* in_sizes, int n_in,
                              void* d_out, int out_size)
{
    const float* context = (const float*)d_in[0];
    const int*   dec     = (const int*)d_in[1];
    const float* h0      = (const float*)d_in[2];
    const float* c0      = (const float*)d_in[3];
    const float* emb     = (const float*)d_in[4];
    const float* Wih     = (const float*)d_in[5];
    const float* Whh     = (const float*)d_in[6];
    const float* bih     = (const float*)d_in[7];
    const float* bhh     = (const float*)d_in[8];
    const float* Wc      = (const float*)d_in[9];
    const float* bc      = (const float*)d_in[10];
    float* out = (float*)d_out;

    float *p_x, *p_g0ih, *p_outs, *p_b0;
    cudaGetSymbolAddress((void**)&p_x,    d_x);
    cudaGetSymbolAddress((void**)&p_g0ih, d_g0ih);
    cudaGetSymbolAddress((void**)&p_outs, d_outs);
    cudaGetSymbolAddress((void**)&p_b0,   d_bias0);

    reset_kernel<<<1, 1>>>();
    prep_kernel<<<(2*Bz*Hz + 255)/256, 256>>>(bih, bhh, h0, c0);
    embed_kernel<<<(Tz*Bz*Hz + 255)/256, 256>>>(dec, emb);

    // layer0 ih gates for ALL timesteps: [T*B, G] = x @ Wih0^T + (bih0+bhh0)
    {
        dim3 grid(Gz/128, (Tz*Bz)/128);
        gemm_abt<<<grid, 256>>>(p_x, Wih, p_b0, p_g0ih, Tz*Bz, Gz, Hz);
    }

    // persistent scan
    scan_kernel<<<NBLK, NTHR>>>(context, Whh, Wih);

    // logits: [B*T, V] = outs @ Wc^T + bc
    {
        dim3 grid(Vz/128, (Bz*Tz)/128);
        gemm_abt<<<grid, 256>>>(p_outs, Wc, bc, out, Bz*Tz, Vz, Hz);
    }

    if ((long long)out_size >= (long long)Bz*Tz*Vz + 4LL*Bz*Hz) {
        tail_kernel<<<(4*Bz*Hz + 255)/256, 256>>>(out);
    }
}

// round 8
// speedup vs baseline: 1.2981x; 1.2981x over previous
#include <cuda_runtime.h>
#include <cuda_bf16.h>
#include <math.h>
#include <stdint.h>

#define Bz 32
#define Tz 64
#define Sz 128
#define Hz 512
#define Vz 32000
#define Gz 2048   // 4*H
#define NBLK 128
#define NTHR 256

// ---------------- device scratch ----------------
__device__ __align__(16) float d_x[Tz*Bz*Hz];
__device__ __align__(16) float d_g0ih[Tz*Bz*Gz];
__device__ __align__(16) float d_h0buf[2*Bz*Hz];
__device__ __align__(16) float d_h1buf[2*Bz*Hz];
__device__ __align__(16) float d_cstate[2*Bz*Hz];
__device__ __align__(16) float d_cat1[Bz*Hz];
__device__ __align__(16) float d_attq[Bz*Hz];
__device__ __align__(16) float d_outs[Bz*Tz*Hz];
__device__ float d_bias0[Gz];
__device__ float d_bias1[Gz];
__device__ unsigned d_bar_cnt;
// bf16 hi/lo splits for tensor-core logits GEMM
__device__ __align__(16) __nv_bfloat16 d_Wc_hi[(size_t)Vz*Hz];
__device__ __align__(16) __nv_bfloat16 d_Wc_lo[(size_t)Vz*Hz];
__device__ __align__(16) __nv_bfloat16 d_out_hi[Bz*Tz*Hz];
__device__ __align__(16) __nv_bfloat16 d_out_lo[Bz*Tz*Hz];

__device__ __forceinline__ float sigf(float x) { return 1.f / (1.f + expf(-x)); }

// ---------------- packed f32x2 helpers ----------------
__device__ __forceinline__ void ffma2(unsigned long long &d,
                                      unsigned long long a,
                                      unsigned long long b)
{
    asm("fma.rn.f32x2 %0, %1, %2, %0;" : "+l"(d) : "l"(a), "l"(b));
}
__device__ __forceinline__ unsigned long long dup2(float x)
{
    unsigned long long r;
    asm("mov.b64 %0, {%1, %1};" : "=l"(r) : "r"(__float_as_uint(x)));
    return r;
}
__device__ __forceinline__ float2 unpack2(unsigned long long v)
{
    unsigned lo, hi;
    asm("mov.b64 {%0, %1}, %2;" : "=r"(lo), "=r"(hi) : "l"(v));
    return make_float2(__uint_as_float(lo), __uint_as_float(hi));
}

// ---------------- mma.sync / ldmatrix helpers (arch-generic, sm_80+) ---------
__device__ __forceinline__ uint32_t smem_u32(const void* p) {
    uint32_t a;
    asm("{ .reg .u64 t; cvta.to.shared.u64 t, %1; cvt.u32.u64 %0, t; }" : "=r"(a) : "l"(p));
    return a;
}
__device__ __forceinline__ void ldsm4(uint32_t (&r)[4], uint32_t addr)
{
    asm volatile("ldmatrix.sync.aligned.m8n8.x4.shared.b16 {%0,%1,%2,%3}, [%4];"
                 : "=r"(r[0]), "=r"(r[1]), "=r"(r[2]), "=r"(r[3]) : "r"(addr));
}
__device__ __forceinline__ void mma_bf16(float (&c)[4], const uint32_t (&a)[4],
                                         const uint32_t* b)
{
    asm volatile(
        "mma.sync.aligned.m16n8k16.row.col.f32.bf16.bf16.f32 "
        "{%0,%1,%2,%3}, {%4,%5,%6,%7}, {%8,%9}, {%0,%1,%2,%3};"
        : "+f"(c[0]), "+f"(c[1]), "+f"(c[2]), "+f"(c[3])
        : "r"(a[0]), "r"(a[1]), "r"(a[2]), "r"(a[3]), "r"(b[0]), "r"(b[1]));
}

// ---------------- grid barrier ----------------
__device__ __forceinline__ void gbar(unsigned &nbar)
{
    nbar++;
    __syncthreads();
    if (threadIdx.x == 0) {
        __threadfence();
        atomicAdd(&d_bar_cnt, 1u);
        unsigned target = nbar * (unsigned)NBLK;
        while (*(volatile unsigned*)&d_bar_cnt < target) __nanosleep(32);
    }
    __syncthreads();
}

__global__ void reset_kernel() { d_bar_cnt = 0u; }

// ---------------- prep ----------------
__global__ void prep_kernel(const float* __restrict__ bih, const float* __restrict__ bhh,
                            const float* __restrict__ h0, const float* __restrict__ c0)
{
    int i = blockIdx.x * blockDim.x + threadIdx.x;
    if (i < Gz) {
        d_bias0[i] = bih[i] + bhh[i];
        d_bias1[i] = bih[Gz + i] + bhh[Gz + i];
    }
    if (i < Bz*Hz) {
        d_h0buf[i] = h0[i];
        d_h1buf[i] = h0[Bz*Hz + i];
    }
    if (i < 2*Bz*Hz) d_cstate[i] = c0[i];
}

// ---------------- hi/lo bf16 split ----------------
__global__ void split_kernel(const float* __restrict__ src,
                             __nv_bfloat16* __restrict__ hi,
                             __nv_bfloat16* __restrict__ lo, size_t n)
{
    size_t i = (size_t)blockIdx.x * blockDim.x + threadIdx.x;
    if (i >= n) return;
    float v = src[i];
    __nv_bfloat16 h = __float2bfloat16(v);
    hi[i] = h;
    lo[i] = __float2bfloat16(v - __bfloat162float(h));
}

// ---------------- embedding ----------------
__global__ void embed_kernel(const int* __restrict__ ids32, const float* __restrict__ emb)
{
    int i = blockIdx.x * blockDim.x + threadIdx.x;
    if (i >= Tz*Bz*Hz) return;
    bool is64 = (ids32[1] == 0) && (ids32[3] == 0) && (ids32[5] == 0);
    int h = i % Hz;
    int tb = i / Hz;
    int b = tb % Bz;
    int t = tb / Bz;
    int idx = b*Tz + t;
    int id = is64 ? ids32[2*idx] : ids32[idx];
    if (id < 0 || id >= Vz) id = 0;
    d_x[i] = (id == 0) ? 0.f : emb[(size_t)id*Hz + h];
}

// ---------------- fp32 GEMM (g0ih precompute): C = A * B^T + bias ------------
__global__ __launch_bounds__(256)
void gemm_abt(const float* __restrict__ A, const float* __restrict__ Bm,
              const float* __restrict__ bias, float* __restrict__ C,
              int M, int N, int K)
{
    __shared__ __align__(16) float As[16][128];
    __shared__ __align__(16) float Bs[16][64];

    const int m0 = blockIdx.y * 128;
    const int n0 = blockIdx.x * 64;
    const int tid = threadIdx.x;
    const int tx = tid & 15;
    const int ty = tid >> 4;

    unsigned long long acc2[4][4];
#pragma unroll
    for (int i = 0; i < 4; ++i)
#pragma unroll
        for (int j = 0; j < 4; ++j) acc2[i][j] = 0ull;

    const int r0 = tid >> 2;
    const int kq = (tid & 3) * 4;

    for (int k0 = 0; k0 < K; k0 += 16) {
        {
            float4 v0 = *(const float4*)&A[(size_t)(m0 + r0)*K + k0 + kq];
            float4 v1 = *(const float4*)&A[(size_t)(m0 + r0 + 64)*K + k0 + kq];
            As[kq+0][r0] = v0.x; As[kq+1][r0] = v0.y;
            As[kq+2][r0] = v0.z; As[kq+3][r0] = v0.w;
            As[kq+0][r0+64] = v1.x; As[kq+1][r0+64] = v1.y;
            As[kq+2][r0+64] = v1.z; As[kq+3][r0+64] = v1.w;
        }
        if (r0 < 64) {
            float4 v = *(const float4*)&Bm[(size_t)(n0 + r0)*K + k0 + kq];
            Bs[kq+0][r0] = v.x; Bs[kq+1][r0] = v.y;
            Bs[kq+2][r0] = v.z; Bs[kq+3][r0] = v.w;
        }
        __syncthreads();
#pragma unroll
        for (int kk = 0; kk < 16; ++kk) {
            ulonglong2 pa = *(const ulonglong2*)&As[kk][ty*8];
            ulonglong2 pb = *(const ulonglong2*)&As[kk][ty*8 + 4];
            unsigned long long ap[4] = { pa.x, pa.y, pb.x, pb.y };
            float4 bq = *(const float4*)&Bs[kk][tx*4];
            unsigned long long bd[4] = { dup2(bq.x), dup2(bq.y), dup2(bq.z), dup2(bq.w) };
#pragma unroll
            for (int i2 = 0; i2 < 4; ++i2)
#pragma unroll
                for (int j = 0; j < 4; ++j) ffma2(acc2[i2][j], ap[i2], bd[j]);
        }
        __syncthreads();
    }

    const int n = n0 + tx*4;
    float4 bv = make_float4(0.f, 0.f, 0.f, 0.f);
    if (bias) { bv.x = bias[n]; bv.y = bias[n+1]; bv.z = bias[n+2]; bv.w = bias[n+3]; }
#pragma unroll
    for (int i2 = 0; i2 < 4; ++i2) {
        float2 c0 = unpack2(acc2[i2][0]);
        float2 c1 = unpack2(acc2[i2][1]);
        float2 c2 = unpack2(acc2[i2][2]);
        float2 c3 = unpack2(acc2[i2][3]);
        int m = m0 + ty*8 + 2*i2;
        *(float4*)&C[(size_t)m*N + n]     = make_float4(c0.x+bv.x, c1.x+bv.y, c2.x+bv.z, c3.x+bv.w);
        *(float4*)&C[(size_t)(m+1)*N + n] = make_float4(c0.y+bv.x, c1.y+bv.y, c2.y+bv.z, c3.y+bv.w);
    }
}

// ---------------- mma.sync bf16 logits GEMM: C = outs @ Wc^T + bc -------------
// Split: C = Ah*Bh + Ah*Bl + Al*Bh (fp32 accum). 128x128 CTA tile, 8 warps
// (2m x 4n), each 64x32. K chunks of 64 in smem (stride 72 halves, pad kills
// ldmatrix bank conflicts).
#define KC   64
#define KCP  72   // padded stride in halves

__global__ void __launch_bounds__(256)
logits_mma_kernel(const __nv_bfloat16* __restrict__ Ahi, const __nv_bfloat16* __restrict__ Alo,
                  const __nv_bfloat16* __restrict__ Bhi, const __nv_bfloat16* __restrict__ Blo,
                  const float* __restrict__ bias, float* __restrict__ C)
{
    extern __shared__ __align__(16) __nv_bfloat16 sm[];
    __nv_bfloat16* sAh = sm;                 // [128][KCP]
    __nv_bfloat16* sAl = sm + 128*KCP;
    __nv_bfloat16* sBh = sm + 2*128*KCP;
    __nv_bfloat16* sBl = sm + 3*128*KCP;

    const int tid  = threadIdx.x;
    const int lane = tid & 31;
    const int wid  = tid >> 5;
    const int wm   = wid >> 2;     // 0..1  (64 rows each)
    const int wn   = wid & 3;      // 0..3  (32 cols each)
    const int n0   = blockIdx.x * 128;
    const int m0   = blockIdx.y * 128;

    float acc[4][4][4];
#pragma unroll
    for (int i = 0; i < 4; ++i)
#pragma unroll
        for (int j = 0; j < 4; ++j)
#pragma unroll
            for (int v = 0; v < 4; ++v) acc[i][j][v] = 0.f;

    // global load mapping: row r = tid>>1 (2 threads/row), 4 uint4 each
    const int gr = tid >> 1;
    const int gs = (tid & 1) * 4;

    // ldmatrix base addresses (bytes)
    const uint32_t uAh = smem_u32(sAh), uAl = smem_u32(sAl);
    const uint32_t uBh = smem_u32(sBh), uBl = smem_u32(sBl);

    for (int k0 = 0; k0 < Hz; k0 += KC) {
        // ---- stage chunk: 4 arrays x 128 rows x 64 halves ----
        {
            const uint4* gAh = (const uint4*)(Ahi + (size_t)(m0 + gr)*Hz + k0);
            const uint4* gAl = (const uint4*)(Alo + (size_t)(m0 + gr)*Hz + k0);
            const uint4* gBh = (const uint4*)(Bhi + (size_t)(n0 + gr)*Hz + k0);
            const uint4* gBl = (const uint4*)(Blo + (size_t)(n0 + gr)*Hz + k0);
#pragma unroll
            for (int i = 0; i < 4; ++i) {
                int seg = gs + i;
                uint32_t so = gr*KCP + seg*8;   // halves
                *(uint4*)(sAh + so) = gAh[seg];
                *(uint4*)(sAl + so) = gAl[seg];
                *(uint4*)(sBh + so) = gBh[seg];
                *(uint4*)(sBl + so) = gBl[seg];
            }
        }
        __syncthreads();

#pragma unroll
        for (int ks = 0; ks < KC/16; ++ks) {
            // A fragment addresses: row wm*64 + mt*16 + (lane&15), col ks*16 + ((lane>>4)<<3)
            uint32_t fAh[4][4], fAl[4][4], fBh[4][2], fBl[4][2];
            const int arow = wm*64 + (lane & 15);
            const int acol = ks*16 + ((lane >> 4) << 3);
#pragma unroll
            for (int mt = 0; mt < 4; ++mt) {
                uint32_t off = ((arow + mt*16)*KCP + acol) * 2;
                ldsm4(fAh[mt], uAh + off);
                ldsm4(fAl[mt], uAl + off);
            }
            // B fragments: 2 n-tiles per ldmatrix.x4
            const int brow = wn*32 + (lane & 7) + ((lane >> 4) << 3);
            const int bcol = ks*16 + (lane & 8);
#pragma unroll
            for (int p = 0; p < 2; ++p) {
                uint32_t off = ((brow + p*16)*KCP + bcol) * 2;
                uint32_t t4[4];
                ldsm4(t4, uBh + off);
                fBh[2*p][0] = t4[0]; fBh[2*p][1] = t4[1];
                fBh[2*p+1][0] = t4[2]; fBh[2*p+1][1] = t4[3];
                ldsm4(t4, uBl + off);
                fBl[2*p][0] = t4[0]; fBl[2*p][1] = t4[1];
                fBl[2*p+1][0] = t4[2]; fBl[2*p+1][1] = t4[3];
            }
#pragma unroll
            for (int mt = 0; mt < 4; ++mt)
#pragma unroll
                for (int nt = 0; nt < 4; ++nt) mma_bf16(acc[mt][nt], fAh[mt], fBh[nt]);
#pragma unroll
            for (int mt = 0; mt < 4; ++mt)
#pragma unroll
                for (int nt = 0; nt < 4; ++nt) mma_bf16(acc[mt][nt], fAh[mt], fBl[nt]);
#pragma unroll
            for (int mt = 0; mt < 4; ++mt)
#pragma unroll
                for (int nt = 0; nt < 4; ++nt) mma_bf16(acc[mt][nt], fAl[mt], fBh[nt]);
        }
        __syncthreads();
    }

    // epilogue: c0,c1 -> (row gid, cols tig*2,+1); c2,c3 -> row gid+8
    const int gid = lane >> 2;
    const int tig = lane & 3;
#pragma unroll
    for (int mt = 0; mt < 4; ++mt) {
        int mA = m0 + wm*64 + mt*16 + gid;
#pragma unroll
        for (int nt = 0; nt < 4; ++nt) {
            int n = n0 + wn*32 + nt*8 + tig*2;
            float2 bv = *(const float2*)&bias[n];
            float2 v0 = make_float2(acc[mt][nt][0] + bv.x, acc[mt][nt][1] + bv.y);
            float2 v1 = make_float2(acc[mt][nt][2] + bv.x, acc[mt][nt][3] + bv.y);
            *(float2*)&C[(size_t)mA*Vz + n]       = v0;
            *(float2*)&C[(size_t)(mA+8)*Vz + n]   = v1;
        }
    }
}

// ---------------- persistent scan (FFMA2 gate GEMVs) ----------------
__global__ void __launch_bounds__(NTHR, 1)
scan_kernel(const float* __restrict__ ctx, const float* __restrict__ Whh,
            const float* __restrict__ Wih)
{
    __shared__ __align__(16) float hbuf[8192];
    __shared__ float sg[16][33];
    __shared__ __align__(16) float attq_s[Hz];
    __shared__ float sc_s[Sz];
    __shared__ float s_part[NTHR];
    __shared__ float s_lse;

    const int tid  = threadIdx.x;
    const int lane = tid & 31;
    const int w    = tid >> 5;
    const int blk  = blockIdx.x;
    const int j0   = blk * 4;
    const int cb   = blk >> 2;
    const int cq   = blk & 3;

    const int lr0 = 2*w, lr1 = 2*w + 1;
    const int n0 = (lr0 >> 2)*Hz + j0 + (lr0 & 3);
    const int n1 = (lr1 >> 2)*Hz + j0 + (lr1 & 3);

    // weight rows as packed f32x2 (memory layout of float4 = 2 x f32x2)
    ulonglong2 wA0[4], wA1[4], wB0[8], wB1[8];
    {
        const ulonglong2* W0 = (const ulonglong2*)(Whh + (size_t)n0*Hz);
        const ulonglong2* W1 = (const ulonglong2*)(Whh + (size_t)n1*Hz);
#pragma unroll
        for (int i = 0; i < 4; ++i) { wA0[i] = W0[lane + 32*i]; wA1[i] = W1[lane + 32*i]; }
        const ulonglong2* I0 = (const ulonglong2*)(Wih + (size_t)(Gz + n0)*Hz);
        const ulonglong2* I1 = (const ulonglong2*)(Wih + (size_t)(Gz + n1)*Hz);
        const ulonglong2* H0 = (const ulonglong2*)(Whh + (size_t)(Gz + n0)*Hz);
        const ulonglong2* H1 = (const ulonglong2*)(Whh + (size_t)(Gz + n1)*Hz);
#pragma unroll
        for (int i = 0; i < 4; ++i) {
            wB0[i]   = I0[lane + 32*i];  wB1[i]   = I1[lane + 32*i];
            wB0[4+i] = H0[lane + 32*i];  wB1[4+i] = H1[lane + 32*i];
        }
    }

    unsigned nbar = 0;
    float4* hb4 = (float4*)hbuf;
    const ulonglong2* hb2 = (const ulonglong2*)hbuf;

    for (int t = 0; t < Tz; ++t) {
        const int p = t & 1;
        const float* h0p = d_h0buf + p*Bz*Hz;
        float*       h0n = d_h0buf + (p^1)*Bz*Hz;
        const float* h1p = d_h1buf + p*Bz*Hz;
        float*       h1n = d_h1buf + (p^1)*Bz*Hz;

        // Phase A
        {
            const float4* Hp = (const float4*)h0p;
            for (int chunk = 0; chunk < 2; ++chunk) {
#pragma unroll
                for (int idx = tid; idx < 2048; idx += NTHR)
                    hb4[idx] = __ldcg(&Hp[chunk*2048 + idx]);
                __syncthreads();
#pragma unroll 2
                for (int bl = 0; bl < 16; ++bl) {
                    unsigned long long a0 = 0ull, a1 = 0ull;
                    const ulonglong2* hr = hb2 + bl*128;
#pragma unroll
                    for (int i = 0; i < 4; ++i) {
                        ulonglong2 h2 = hr[lane + 32*i];
                        ffma2(a0, h2.x, wA0[i].x); ffma2(a0, h2.y, wA0[i].y);
                        ffma2(a1, h2.x, wA1[i].x); ffma2(a1, h2.y, wA1[i].y);
                    }
                    float2 f0 = unpack2(a0), f1 = unpack2(a1);
                    float s0 = f0.x + f0.y, s1 = f1.x + f1.y;
#pragma unroll
                    for (int o = 16; o; o >>= 1) {
                        s0 += __shfl_xor_sync(0xffffffffu, s0, o);
                        s1 += __shfl_xor_sync(0xffffffffu, s1, o);
                    }
                    if (lane == 0) { sg[lr0][chunk*16 + bl] = s0; sg[lr1][chunk*16 + bl] = s1; }
                }
                __syncthreads();
            }
            if (tid < 128) {
                int b = tid >> 2, jj = tid & 3;
                int j = j0 + jj;
                const float* seed = d_g0ih + ((size_t)t*Bz + b)*Gz;
                float gi = sg[0  + jj][b] + seed[j];
                float gf = sg[4  + jj][b] + seed[Hz + j];
                float gg = sg[8  + jj][b] + seed[2*Hz + j];
                float go = sg[12 + jj][b] + seed[3*Hz + j];
                int ci = b*Hz + j;
                float c = sigf(gf)*d_cstate[ci] + sigf(gi)*tanhf(gg);
                float h = sigf(go)*tanhf(c);
                d_cstate[ci] = c;
                __stcg(&h0n[ci], h);
                __stcg(&d_cat1[ci], h + d_x[((size_t)t*Bz + b)*Hz + j]);
            }
        }
        gbar(nbar);

        // Phase B
        {
            for (int half = 0; half < 2; ++half) {
                const float4* src = half ? (const float4*)h1p : (const float4*)d_cat1;
                const ulonglong2* wr0 = half ? (wB0 + 4) : wB0;
                const ulonglong2* wr1 = half ? (wB1 + 4) : wB1;
                for (int chunk = 0; chunk < 2; ++chunk) {
#pragma unroll
                    for (int idx = tid; idx < 2048; idx += NTHR)
                        hb4[idx] = __ldcg(&src[chunk*2048 + idx]);
                    __syncthreads();
#pragma unroll 2
                    for (int bl = 0; bl < 16; ++bl) {
                        unsigned long long a0 = 0ull, a1 = 0ull;
                        const ulonglong2* hr = hb2 + bl*128;
#pragma unroll
                        for (int i = 0; i < 4; ++i) {
                            ulonglong2 h2 = hr[lane + 32*i];
                            ffma2(a0, h2.x, wr0[i].x); ffma2(a0, h2.y, wr0[i].y);
                            ffma2(a1, h2.x, wr1[i].x); ffma2(a1, h2.y, wr1[i].y);
                        }
                        float2 f0 = unpack2(a0), f1 = unpack2(a1);
                        float s0 = f0.x + f0.y, s1 = f1.x + f1.y;
#pragma unroll
                        for (int o = 16; o; o >>= 1) {
                            s0 += __shfl_xor_sync(0xffffffffu, s0, o);
                            s1 += __shfl_xor_sync(0xffffffffu, s1, o);
                        }
                        if (lane == 0) {
                            int b = chunk*16 + bl;
                            if (half == 0) { sg[lr0][b] = s0; sg[lr1][b] = s1; }
                            else           { sg[lr0][b] += s0; sg[lr1][b] += s1; }
                        }
                    }
                    __syncthreads();
                }
            }
            if (tid < 128) {
                int b = tid >> 2, jj = tid & 3;
                int j = j0 + jj;
                float gi = sg[0  + jj][b] + d_bias1[j];
                float gf = sg[4  + jj][b] + d_bias1[Hz + j];
                float gg = sg[8  + jj][b] + d_bias1[2*Hz + j];
                float go = sg[12 + jj][b] + d_bias1[3*Hz + j];
                int ci = Bz*Hz + b*Hz + j;
                float c = sigf(gf)*d_cstate[ci] + sigf(gi)*tanhf(gg);
                float h = sigf(go)*tanhf(c);
                d_cstate[ci] = c;
                __stcg(&h1n[b*Hz + j], h);
                __stcg(&d_attq[b*Hz + j], h + __ldcg(&d_cat1[b*Hz + j]));
            }
        }
        gbar(nbar);

        // Phase C
        {
            for (int i = tid; i < Hz; i += NTHR) attq_s[i] = __ldcg(&d_attq[cb*Hz + i]);
            __syncthreads();

            const float4* A4 = (const float4*)attq_s;
            for (int s = w*16; s < w*16 + 16; ++s) {
                const float4* C4 = (const float4*)(ctx + ((size_t)cb*Sz + s)*Hz);
                float acc = 0.f;
#pragma unroll
                for (int i = 0; i < 4; ++i) {
                    float4 c4 = C4[lane + 32*i];
                    float4 a4 = A4[lane + 32*i];
                    acc += c4.x*a4.x + c4.y*a4.y + c4.z*a4.z + c4.w*a4.w;
                }
#pragma unroll
                for (int o = 16; o; o >>= 1) acc += __shfl_xor_sync(0xffffffffu, acc, o);
                if (lane == 0) sc_s[s] = acc;
            }
            __syncthreads();

            if (w == 0) {
                float m = -1e30f;
                for (int s = lane; s < Sz; s += 32) m = fmaxf(m, sc_s[s]);
#pragma unroll
                for (int o = 16; o; o >>= 1) m = fmaxf(m, __shfl_xor_sync(0xffffffffu, m, o));
                float sm = 0.f;
                for (int s = lane; s < Sz; s += 32) sm += expf(sc_s[s] - m);
#pragma unroll
                for (int o = 16; o; o >>= 1) sm += __shfl_xor_sync(0xffffffffu, sm, o);
                if (lane == 0) s_lse = m + logf(sm);
            }
            __syncthreads();
            float lse = s_lse;

            int h = cq*128 + (tid & 127);
            int sgrp = tid >> 7;
            float acc = 0.f;
            for (int s = sgrp*64; s < sgrp*64 + 64; ++s)
                acc += ctx[((size_t)cb*Sz + s)*Hz + h] * (sc_s[s] - lse);
            s_part[tid] = acc;
            __syncthreads();
            if (tid < 128)
                d_outs[((size_t)cb*Tz + t)*Hz + h] = s_part[tid] + s_part[tid + 128];
            __syncthreads();
        }
    }
}

// ---------------- tail: hT, cT ----------------
__global__ void tail_kernel(float* __restrict__ out)
{
    int i = blockIdx.x * blockDim.x + threadIdx.x;
    const size_t base = (size_t)Bz*Tz*Vz;
    if (i < Bz*Hz)                 out[base + i] = d_h0buf[i];
    else if (i < 2*Bz*Hz)          out[base + i] = d_h1buf[i - Bz*Hz];
    else if (i < 4*Bz*Hz)          out[base + i] = d_cstate[i - 2*Bz*Hz];
}

// ---------------- launch ----------------
extern "C" void kernel_launch(void* const* d_in, const int* in_sizes, int n_in,
                              void* d_out, int out_size)
{
    const float* context = (const float*)d_in[0];
    const int*   dec     = (const int*)d_in[1];
    const float* h0      = (const float*)d_in[2];
    const float* c0      = (const float*)d_in[3];
    const float* emb     = (const float*)d_in[4];
    const float* Wih     = (const float*)d_in[5];
    const float* Whh     = (const float*)d_in[6];
    const float* bih     = (const float*)d_in[7];
    const float* bhh     = (const float*)d_in[8];
    const float* Wc      = (const float*)d_in[9];
    const float* bc      = (const float*)d_in[10];
    float* out = (float*)d_out;

    float *p_x, *p_g0ih, *p_outs, *p_b0;
    __nv_bfloat16 *p_wch, *p_wcl, *p_oh, *p_ol;
    cudaGetSymbolAddress((void**)&p_x,    d_x);
    cudaGetSymbolAddress((void**)&p_g0ih, d_g0ih);
    cudaGetSymbolAddress((void**)&p_outs, d_outs);
    cudaGetSymbolAddress((void**)&p_b0,   d_bias0);
    cudaGetSymbolAddress((void**)&p_wch,  d_Wc_hi);
    cudaGetSymbolAddress((void**)&p_wcl,  d_Wc_lo);
    cudaGetSymbolAddress((void**)&p_oh,   d_out_hi);
    cudaGetSymbolAddress((void**)&p_ol,   d_out_lo);

    const int SMEM_MMA = 4 * 128 * KCP * 2;   // 73728 bytes
    cudaFuncSetAttribute(logits_mma_kernel,
                         cudaFuncAttributeMaxDynamicSharedMemorySize, SMEM_MMA);

    reset_kernel<<<1, 1>>>();
    prep_kernel<<<(2*Bz*Hz + 255)/256, 256>>>(bih, bhh, h0, c0);
    embed_kernel<<<(Tz*Bz*Hz + 255)/256, 256>>>(dec, emb);

    // Wc hi/lo split
    {
        size_t n = (size_t)Vz*Hz;
        split_kernel<<<(unsigned)((n + 255)/256), 256>>>(Wc, p_wch, p_wcl, n);
    }

    // layer0 ih gates for ALL timesteps
    {
        dim3 grid(Gz/64, (Tz*Bz)/128);
        gemm_abt<<<grid, 256>>>(p_x, Wih, p_b0, p_g0ih, Tz*Bz, Gz, Hz);
    }

    // persistent scan
    scan_kernel<<<NBLK, NTHR>>>(context, Whh, Wih);

    // outs hi/lo split
    {
        size_t n = (size_t)Bz*Tz*Hz;
        split_kernel<<<(unsigned)((n + 255)/256), 256>>>(p_outs, p_oh, p_ol, n);
    }

    // logits via mma.sync bf16 split GEMM
    {
        dim3 grid(Vz/128, (Bz*Tz)/128);
        logits_mma_kernel<<<grid, 256, SMEM_MMA>>>(p_oh, p_ol, p_wch, p_wcl, bc, out);
    }

    if ((long long)out_size >= (long long)Bz*Tz*Vz + 4LL*Bz*Hz) {
        tail_kernel<<<(4*Bz*Hz + 255)/256, 256>>>(out);
    }
}

// round 9
// speedup vs baseline: 1.3725x; 1.0573x over previous
#include <cuda_runtime.h>
#include <cuda_bf16.h>
#include <math.h>
#include <stdint.h>

#define Bz 32
#define Tz 64
#define Sz 128
#define Hz 512
#define Vz 32000
#define Gz 2048   // 4*H
#define NBLK 128
#define NTHR 256

// ---------------- device scratch ----------------
__device__ __align__(16) float d_x[Tz*Bz*Hz];
__device__ __align__(16) float d_g0ih[Tz*Bz*Gz];
__device__ __align__(16) float d_h0buf[2*Bz*Hz];
__device__ __align__(16) float d_h1buf[2*Bz*Hz];
__device__ __align__(16) float d_cstate[2*Bz*Hz];
__device__ __align__(16) float d_cat1[Bz*Hz];
__device__ __align__(16) float d_attq[Bz*Hz];
__device__ float d_bias0[Gz];
__device__ float d_bias1[Gz];
__device__ unsigned d_bar_cnt;
// bf16 hi/lo splits
__device__ __align__(16) __nv_bfloat16 d_Wc_hi[(size_t)Vz*Hz];
__device__ __align__(16) __nv_bfloat16 d_Wc_lo[(size_t)Vz*Hz];
__device__ __align__(16) __nv_bfloat16 d_out_hi[Bz*Tz*Hz];
__device__ __align__(16) __nv_bfloat16 d_out_lo[Bz*Tz*Hz];
__device__ __align__(16) __nv_bfloat16 d_x_hi[Tz*Bz*Hz];
__device__ __align__(16) __nv_bfloat16 d_x_lo[Tz*Bz*Hz];
__device__ __align__(16) __nv_bfloat16 d_Wih0_hi[Gz*Hz];
__device__ __align__(16) __nv_bfloat16 d_Wih0_lo[Gz*Hz];

__device__ __forceinline__ float sigf(float x) { return 1.f / (1.f + expf(-x)); }

// ---------------- packed f32x2 helpers ----------------
__device__ __forceinline__ void ffma2(unsigned long long &d,
                                      unsigned long long a,
                                      unsigned long long b)
{
    asm("fma.rn.f32x2 %0, %1, %2, %0;" : "+l"(d) : "l"(a), "l"(b));
}
__device__ __forceinline__ float2 unpack2(unsigned long long v)
{
    unsigned lo, hi;
    asm("mov.b64 {%0, %1}, %2;" : "=r"(lo), "=r"(hi) : "l"(v));
    return make_float2(__uint_as_float(lo), __uint_as_float(hi));
}

// ---------------- mma.sync / ldmatrix / cp.async helpers ----------------
__device__ __forceinline__ uint32_t smem_u32(const void* p) {
    uint32_t a;
    asm("{ .reg .u64 t; cvta.to.shared.u64 t, %1; cvt.u32.u64 %0, t; }" : "=r"(a) : "l"(p));
    return a;
}
__device__ __forceinline__ void ldsm4(uint32_t (&r)[4], uint32_t addr)
{
    asm volatile("ldmatrix.sync.aligned.m8n8.x4.shared.b16 {%0,%1,%2,%3}, [%4];"
                 : "=r"(r[0]), "=r"(r[1]), "=r"(r[2]), "=r"(r[3]) : "r"(addr));
}
__device__ __forceinline__ void mma_bf16(float (&c)[4], const uint32_t (&a)[4],
                                         const uint32_t* b)
{
    asm volatile(
        "mma.sync.aligned.m16n8k16.row.col.f32.bf16.bf16.f32 "
        "{%0,%1,%2,%3}, {%4,%5,%6,%7}, {%8,%9}, {%0,%1,%2,%3};"
        : "+f"(c[0]), "+f"(c[1]), "+f"(c[2]), "+f"(c[3])
        : "r"(a[0]), "r"(a[1]), "r"(a[2]), "r"(a[3]), "r"(b[0]), "r"(b[1]));
}
#define CP_ASYNC16(dst, src) \
    asm volatile("cp.async.ca.shared.global [%0], [%1], 16;" :: "r"(dst), "l"(src))
#define CP_COMMIT() asm volatile("cp.async.commit_group;" ::: "memory")
#define CP_WAIT(n)  asm volatile("cp.async.wait_group %0;" :: "n"(n) : "memory")

// ---------------- grid barrier ----------------
__device__ __forceinline__ void gbar(unsigned &nbar)
{
    nbar++;
    __syncthreads();
    if (threadIdx.x == 0) {
        __threadfence();
        atomicAdd(&d_bar_cnt, 1u);
        unsigned target = nbar * (unsigned)NBLK;
        while (*(volatile unsigned*)&d_bar_cnt < target) __nanosleep(32);
    }
    __syncthreads();
}

__global__ void reset_kernel() { d_bar_cnt = 0u; }

// ---------------- prep ----------------
__global__ void prep_kernel(const float* __restrict__ bih, const float* __restrict__ bhh,
                            const float* __restrict__ h0, const float* __restrict__ c0)
{
    int i = blockIdx.x * blockDim.x + threadIdx.x;
    if (i < Gz) {
        d_bias0[i] = bih[i] + bhh[i];
        d_bias1[i] = bih[Gz + i] + bhh[Gz + i];
    }
    if (i < Bz*Hz) {
        d_h0buf[i] = h0[i];
        d_h1buf[i] = h0[Bz*Hz + i];
    }
    if (i < 2*Bz*Hz) d_cstate[i] = c0[i];
}

// ---------------- hi/lo bf16 split ----------------
__global__ void split_kernel(const float* __restrict__ src,
                             __nv_bfloat16* __restrict__ hi,
                             __nv_bfloat16* __restrict__ lo, size_t n)
{
    size_t i = (size_t)blockIdx.x * blockDim.x + threadIdx.x;
    if (i >= n) return;
    float v = src[i];
    __nv_bfloat16 h = __float2bfloat16(v);
    hi[i] = h;
    lo[i] = __float2bfloat16(v - __bfloat162float(h));
}

// ---------------- embedding ----------------
__global__ void embed_kernel(const int* __restrict__ ids32, const float* __restrict__ emb)
{
    int i = blockIdx.x * blockDim.x + threadIdx.x;
    if (i >= Tz*Bz*Hz) return;
    bool is64 = (ids32[1] == 0) && (ids32[3] == 0) && (ids32[5] == 0);
    int h = i % Hz;
    int tb = i / Hz;
    int b = tb % Bz;
    int t = tb / Bz;
    int idx = b*Tz + t;
    int id = is64 ? ids32[2*idx] : ids32[idx];
    if (id < 0 || id >= Vz) id = 0;
    float v = (id == 0) ? 0.f : emb[(size_t)id*Hz + h];
    d_x[i] = v;
    __nv_bfloat16 hv = __float2bfloat16(v);
    d_x_hi[i] = hv;
    d_x_lo[i] = __float2bfloat16(v - __bfloat162float(hv));
}

// ---------------- bf16-split mma GEMM: C[M,N] = A @ B^T + bias ---------------
// C = Ah*Bh + Ah*Bl + Al*Bh (fp32 accum). 128x128 CTA tile, 8 warps (2m x 4n),
// K = Hz, chunks of 64 halves; cp.async double-buffered staging.
#define KC   64
#define KCP  72                          // padded stride (halves)
#define BUFB (4*128*KCP*2)               // bytes per stage buffer

__global__ void __launch_bounds__(256)
mma_gemm_kernel(const __nv_bfloat16* __restrict__ Ahi, const __nv_bfloat16* __restrict__ Alo,
                const __nv_bfloat16* __restrict__ Bhi, const __nv_bfloat16* __restrict__ Blo,
                const float* __restrict__ bias, float* __restrict__ C, int ldc)
{
    extern __shared__ __align__(16) char sm_raw[];

    const int tid  = threadIdx.x;
    const int lane = tid & 31;
    const int wid  = tid >> 5;
    const int wm   = wid >> 2;
    const int wn   = wid & 3;
    const int n0   = blockIdx.x * 128;
    const int m0   = blockIdx.y * 128;

    float acc[4][4][4];
#pragma unroll
    for (int i = 0; i < 4; ++i)
#pragma unroll
        for (int j = 0; j < 4; ++j)
#pragma unroll
            for (int v = 0; v < 4; ++v) acc[i][j][v] = 0.f;

    const int gr = tid >> 1;           // staged row
    const int gs = (tid & 1) * 4;      // first of 4 segments (8 halves each)

    const uint32_t smBase = smem_u32(sm_raw);

    // stage chunk c into buffer buf via cp.async (16 x 16B per thread)
    auto stage = [&](int c, int buf) {
        const int k0 = c * KC;
        uint32_t db = smBase + buf*BUFB + (gr*KCP)*2 + gs*16;
        const __nv_bfloat16* pA_h = Ahi + (size_t)(m0 + gr)*Hz + k0 + gs*8;
        const __nv_bfloat16* pA_l = Alo + (size_t)(m0 + gr)*Hz + k0 + gs*8;
        const __nv_bfloat16* pB_h = Bhi + (size_t)(n0 + gr)*Hz + k0 + gs*8;
        const __nv_bfloat16* pB_l = Blo + (size_t)(n0 + gr)*Hz + k0 + gs*8;
#pragma unroll
        for (int i = 0; i < 4; ++i) {
            CP_ASYNC16(db + i*16 + 0*128*KCP*2, pA_h + i*8);
            CP_ASYNC16(db + i*16 + 1*128*KCP*2, pA_l + i*8);
            CP_ASYNC16(db + i*16 + 2*128*KCP*2, pB_h + i*8);
            CP_ASYNC16(db + i*16 + 3*128*KCP*2, pB_l + i*8);
        }
        CP_COMMIT();
    };

    const int NCHUNK = Hz / KC;   // 8
    stage(0, 0);

    for (int c = 0; c < NCHUNK; ++c) {
        if (c + 1 < NCHUNK) { stage(c + 1, (c + 1) & 1); CP_WAIT(1); }
        else                { CP_WAIT(0); }
        __syncthreads();

        const uint32_t bb  = smBase + (c & 1)*BUFB;
        const uint32_t uAh = bb;
        const uint32_t uAl = bb + 1*128*KCP*2;
        const uint32_t uBh = bb + 2*128*KCP*2;
        const uint32_t uBl = bb + 3*128*KCP*2;

#pragma unroll
        for (int ks = 0; ks < KC/16; ++ks) {
            uint32_t fAh[4][4], fAl[4][4], fBh[4][2], fBl[4][2];
            const int arow = wm*64 + (lane & 15);
            const int acol = ks*16 + ((lane >> 4) << 3);
#pragma unroll
            for (int mt = 0; mt < 4; ++mt) {
                uint32_t off = ((arow + mt*16)*KCP + acol) * 2;
                ldsm4(fAh[mt], uAh + off);
                ldsm4(fAl[mt], uAl + off);
            }
            const int brow = wn*32 + (lane & 7) + ((lane >> 4) << 3);
            const int bcol = ks*16 + (lane & 8);
#pragma unroll
            for (int p = 0; p < 2; ++p) {
                uint32_t off = ((brow + p*16)*KCP + bcol) * 2;
                uint32_t t4[4];
                ldsm4(t4, uBh + off);
                fBh[2*p][0] = t4[0]; fBh[2*p][1] = t4[1];
                fBh[2*p+1][0] = t4[2]; fBh[2*p+1][1] = t4[3];
                ldsm4(t4, uBl + off);
                fBl[2*p][0] = t4[0]; fBl[2*p][1] = t4[1];
                fBl[2*p+1][0] = t4[2]; fBl[2*p+1][1] = t4[3];
            }
#pragma unroll
            for (int mt = 0; mt < 4; ++mt)
#pragma unroll
                for (int nt = 0; nt < 4; ++nt) mma_bf16(acc[mt][nt], fAh[mt], fBh[nt]);
#pragma unroll
            for (int mt = 0; mt < 4; ++mt)
#pragma unroll
                for (int nt = 0; nt < 4; ++nt) mma_bf16(acc[mt][nt], fAh[mt], fBl[nt]);
#pragma unroll
            for (int mt = 0; mt < 4; ++mt)
#pragma unroll
                for (int nt = 0; nt < 4; ++nt) mma_bf16(acc[mt][nt], fAl[mt], fBh[nt]);
        }
        __syncthreads();
    }

    const int gid = lane >> 2;
    const int tig = lane & 3;
#pragma unroll
    for (int mt = 0; mt < 4; ++mt) {
        int mA = m0 + wm*64 + mt*16 + gid;
#pragma unroll
        for (int nt = 0; nt < 4; ++nt) {
            int n = n0 + wn*32 + nt*8 + tig*2;
            float2 bv = *(const float2*)&bias[n];
            float2 v0 = make_float2(acc[mt][nt][0] + bv.x, acc[mt][nt][1] + bv.y);
            float2 v1 = make_float2(acc[mt][nt][2] + bv.x, acc[mt][nt][3] + bv.y);
            *(float2*)&C[(size_t)mA*ldc + n]     = v0;
            *(float2*)&C[(size_t)(mA+8)*ldc + n] = v1;
        }
    }
}

// ---------------- persistent scan ----------------
__global__ void __launch_bounds__(NTHR, 1)
scan_kernel(const float* __restrict__ ctx, const float* __restrict__ Whh,
            const float* __restrict__ Wih)
{
    __shared__ __align__(16) float hbuf[8192];
    __shared__ float sg[16][33];
    __shared__ __align__(16) float attq_s[Hz];
    __shared__ float sc_s[Sz];
    __shared__ float s_part[NTHR];
    __shared__ float s_lse;

    const int tid  = threadIdx.x;
    const int lane = tid & 31;
    const int w    = tid >> 5;
    const int blk  = blockIdx.x;
    const int j0   = blk * 4;
    const int cb   = blk >> 2;
    const int cq   = blk & 3;

    const int lr0 = 2*w, lr1 = 2*w + 1;
    const int n0 = (lr0 >> 2)*Hz + j0 + (lr0 & 3);
    const int n1 = (lr1 >> 2)*Hz + j0 + (lr1 & 3);

    ulonglong2 wA0[4], wA1[4], wB0[8], wB1[8];
    {
        const ulonglong2* W0 = (const ulonglong2*)(Whh + (size_t)n0*Hz);
        const ulonglong2* W1 = (const ulonglong2*)(Whh + (size_t)n1*Hz);
#pragma unroll
        for (int i = 0; i < 4; ++i) { wA0[i] = W0[lane + 32*i]; wA1[i] = W1[lane + 32*i]; }
        const ulonglong2* I0 = (const ulonglong2*)(Wih + (size_t)(Gz + n0)*Hz);
        const ulonglong2* I1 = (const ulonglong2*)(Wih + (size_t)(Gz + n1)*Hz);
        const ulonglong2* H0 = (const ulonglong2*)(Whh + (size_t)(Gz + n0)*Hz);
        const ulonglong2* H1 = (const ulonglong2*)(Whh + (size_t)(Gz + n1)*Hz);
#pragma unroll
        for (int i = 0; i < 4; ++i) {
            wB0[i]   = I0[lane + 32*i];  wB1[i]   = I1[lane + 32*i];
            wB0[4+i] = H0[lane + 32*i];  wB1[4+i] = H1[lane + 32*i];
        }
    }

    unsigned nbar = 0;
    float4* hb4 = (float4*)hbuf;
    const ulonglong2* hb2 = (const ulonglong2*)hbuf;

    for (int t = 0; t < Tz; ++t) {
        const int p = t & 1;
        const float* h0p = d_h0buf + p*Bz*Hz;
        float*       h0n = d_h0buf + (p^1)*Bz*Hz;
        const float* h1p = d_h1buf + p*Bz*Hz;
        float*       h1n = d_h1buf + (p^1)*Bz*Hz;

        // Phase A
        {
            const float4* Hp = (const float4*)h0p;
            for (int chunk = 0; chunk < 2; ++chunk) {
#pragma unroll
                for (int idx = tid; idx < 2048; idx += NTHR)
                    hb4[idx] = __ldcg(&Hp[chunk*2048 + idx]);
                __syncthreads();
#pragma unroll 2
                for (int bl = 0; bl < 16; ++bl) {
                    unsigned long long a0 = 0ull, a1 = 0ull;
                    const ulonglong2* hr = hb2 + bl*128;
#pragma unroll
                    for (int i = 0; i < 4; ++i) {
                        ulonglong2 h2 = hr[lane + 32*i];
                        ffma2(a0, h2.x, wA0[i].x); ffma2(a0, h2.y, wA0[i].y);
                        ffma2(a1, h2.x, wA1[i].x); ffma2(a1, h2.y, wA1[i].y);
                    }
                    float2 f0 = unpack2(a0), f1 = unpack2(a1);
                    float s0 = f0.x + f0.y, s1 = f1.x + f1.y;
#pragma unroll
                    for (int o = 16; o; o >>= 1) {
                        s0 += __shfl_xor_sync(0xffffffffu, s0, o);
                        s1 += __shfl_xor_sync(0xffffffffu, s1, o);
                    }
                    if (lane == 0) { sg[lr0][chunk*16 + bl] = s0; sg[lr1][chunk*16 + bl] = s1; }
                }
                __syncthreads();
            }
            if (tid < 128) {
                int b = tid >> 2, jj = tid & 3;
                int j = j0 + jj;
                const float* seed = d_g0ih + ((size_t)t*Bz + b)*Gz;
                float gi = sg[0  + jj][b] + seed[j];
                float gf = sg[4  + jj][b] + seed[Hz + j];
                float gg = sg[8  + jj][b] + seed[2*Hz + j];
                float go = sg[12 + jj][b] + seed[3*Hz + j];
                int ci = b*Hz + j;
                float c = sigf(gf)*d_cstate[ci] + sigf(gi)*tanhf(gg);
                float h = sigf(go)*tanhf(c);
                d_cstate[ci] = c;
                __stcg(&h0n[ci], h);
                __stcg(&d_cat1[ci], h + d_x[((size_t)t*Bz + b)*Hz + j]);
            }
        }
        gbar(nbar);

        // Phase B
        {
            for (int half = 0; half < 2; ++half) {
                const float4* src = half ? (const float4*)h1p : (const float4*)d_cat1;
                const ulonglong2* wr0 = half ? (wB0 + 4) : wB0;
                const ulonglong2* wr1 = half ? (wB1 + 4) : wB1;
                for (int chunk = 0; chunk < 2; ++chunk) {
#pragma unroll
                    for (int idx = tid; idx < 2048; idx += NTHR)
                        hb4[idx] = __ldcg(&src[chunk*2048 + idx]);
                    __syncthreads();
#pragma unroll 2
                    for (int bl = 0; bl < 16; ++bl) {
                        unsigned long long a0 = 0ull, a1 = 0ull;
                        const ulonglong2* hr = hb2 + bl*128;
#pragma unroll
                        for (int i = 0; i < 4; ++i) {
                            ulonglong2 h2 = hr[lane + 32*i];
                            ffma2(a0, h2.x, wr0[i].x); ffma2(a0, h2.y, wr0[i].y);
                            ffma2(a1, h2.x, wr1[i].x); ffma2(a1, h2.y, wr1[i].y);
                        }
                        float2 f0 = unpack2(a0), f1 = unpack2(a1);
                        float s0 = f0.x + f0.y, s1 = f1.x + f1.y;
#pragma unroll
                        for (int o = 16; o; o >>= 1) {
                            s0 += __shfl_xor_sync(0xffffffffu, s0, o);
                            s1 += __shfl_xor_sync(0xffffffffu, s1, o);
                        }
                        if (lane == 0) {
                            int b = chunk*16 + bl;
                            if (half == 0) { sg[lr0][b] = s0; sg[lr1][b] = s1; }
                            else           { sg[lr0][b] += s0; sg[lr1][b] += s1; }
                        }
                    }
                    __syncthreads();
                }
            }
            if (tid < 128) {
                int b = tid >> 2, jj = tid & 3;
                int j = j0 + jj;
                float gi = sg[0  + jj][b] + d_bias1[j];
                float gf = sg[4  + jj][b] + d_bias1[Hz + j];
                float gg = sg[8  + jj][b] + d_bias1[2*Hz + j];
                float go = sg[12 + jj][b] + d_bias1[3*Hz + j];
                int ci = Bz*Hz + b*Hz + j;
                float c = sigf(gf)*d_cstate[ci] + sigf(gi)*tanhf(gg);
                float h = sigf(go)*tanhf(c);
                d_cstate[ci] = c;
                __stcg(&h1n[b*Hz + j], h);
                __stcg(&d_attq[b*Hz + j], h + __ldcg(&d_cat1[b*Hz + j]));
            }
        }
        gbar(nbar);

        // Phase C (writes bf16 hi/lo directly for the logits GEMM)
        {
            for (int i = tid; i < Hz; i += NTHR) attq_s[i] = __ldcg(&d_attq[cb*Hz + i]);
            __syncthreads();

            const float4* A4 = (const float4*)attq_s;
            for (int s = w*16; s < w*16 + 16; ++s) {
                const float4* C4 = (const float4*)(ctx + ((size_t)cb*Sz + s)*Hz);
                float acc = 0.f;
#pragma unroll
                for (int i = 0; i < 4; ++i) {
                    float4 c4 = C4[lane + 32*i];
                    float4 a4 = A4[lane + 32*i];
                    acc += c4.x*a4.x + c4.y*a4.y + c4.z*a4.z + c4.w*a4.w;
                }
#pragma unroll
                for (int o = 16; o; o >>= 1) acc += __shfl_xor_sync(0xffffffffu, acc, o);
                if (lane == 0) sc_s[s] = acc;
            }
            __syncthreads();

            if (w == 0) {
                float m = -1e30f;
                for (int s = lane; s < Sz; s += 32) m = fmaxf(m, sc_s[s]);
#pragma unroll
                for (int o = 16; o; o >>= 1) m = fmaxf(m, __shfl_xor_sync(0xffffffffu, m, o));
                float sm = 0.f;
                for (int s = lane; s < Sz; s += 32) sm += expf(sc_s[s] - m);
#pragma unroll
                for (int o = 16; o; o >>= 1) sm += __shfl_xor_sync(0xffffffffu, sm, o);
                if (lane == 0) s_lse = m + logf(sm);
            }
            __syncthreads();
            float lse = s_lse;

            int h = cq*128 + (tid & 127);
            int sgrp = tid >> 7;
            float acc = 0.f;
            for (int s = sgrp*64; s < sgrp*64 + 64; ++s)
                acc += ctx[((size_t)cb*Sz + s)*Hz + h] * (sc_s[s] - lse);
            s_part[tid] = acc;
            __syncthreads();
            if (tid < 128) {
                float v = s_part[tid] + s_part[tid + 128];
                size_t oi = ((size_t)cb*Tz + t)*Hz + h;
                __nv_bfloat16 hv = __float2bfloat16(v);
                d_out_hi[oi] = hv;
                d_out_lo[oi] = __float2bfloat16(v - __bfloat162float(hv));
            }
            __syncthreads();
        }
    }
}

// ---------------- tail: hT, cT ----------------
__global__ void tail_kernel(float* __restrict__ out)
{
    int i = blockIdx.x * blockDim.x + threadIdx.x;
    const size_t base = (size_t)Bz*Tz*Vz;
    if (i < Bz*Hz)                 out[base + i] = d_h0buf[i];
    else if (i < 2*Bz*Hz)          out[base + i] = d_h1buf[i - Bz*Hz];
    else if (i < 4*Bz*Hz)          out[base + i] = d_cstate[i - 2*Bz*Hz];
}

// ---------------- launch ----------------
extern "C" void kernel_launch(void* const* d_in, const int* in_sizes, int n_in,
                              void* d_out, int out_size)
{
    const float* context = (const float*)d_in[0];
    const int*   dec     = (const int*)d_in[1];
    const float* h0      = (const float*)d_in[2];
    const float* c0      = (const float*)d_in[3];
    const float* emb     = (const float*)d_in[4];
    const float* Wih     = (const float*)d_in[5];
    const float* Whh     = (const float*)d_in[6];
    const float* bih     = (const float*)d_in[7];
    const float* bhh     = (const float*)d_in[8];
    const float* Wc      = (const float*)d_in[9];
    const float* bc      = (const float*)d_in[10];
    float* out = (float*)d_out;

    float *p_x, *p_g0ih, *p_b0;
    __nv_bfloat16 *p_wch, *p_wcl, *p_oh, *p_ol, *p_xh, *p_xl, *p_wih, *p_wil;
    cudaGetSymbolAddress((void**)&p_x,    d_x);
    cudaGetSymbolAddress((void**)&p_g0ih, d_g0ih);
    cudaGetSymbolAddress((void**)&p_b0,   d_bias0);
    cudaGetSymbolAddress((void**)&p_wch,  d_Wc_hi);
    cudaGetSymbolAddress((void**)&p_wcl,  d_Wc_lo);
    cudaGetSymbolAddress((void**)&p_oh,   d_out_hi);
    cudaGetSymbolAddress((void**)&p_ol,   d_out_lo);
    cudaGetSymbolAddress((void**)&p_xh,   d_x_hi);
    cudaGetSymbolAddress((void**)&p_xl,   d_x_lo);
    cudaGetSymbolAddress((void**)&p_wih,  d_Wih0_hi);
    cudaGetSymbolAddress((void**)&p_wil,  d_Wih0_lo);

    const int SMEM_MMA = 2 * BUFB;   // 147456 bytes (double buffer)
    cudaFuncSetAttribute(mma_gemm_kernel,
                         cudaFuncAttributeMaxDynamicSharedMemorySize, SMEM_MMA);

    reset_kernel<<<1, 1>>>();
    prep_kernel<<<(2*Bz*Hz + 255)/256, 256>>>(bih, bhh, h0, c0);
    embed_kernel<<<(Tz*Bz*Hz + 255)/256, 256>>>(dec, emb);

    // splits: Wc, Wih layer0
    {
        size_t n = (size_t)Vz*Hz;
        split_kernel<<<(unsigned)((n + 255)/256), 256>>>(Wc, p_wch, p_wcl, n);
        size_t n2 = (size_t)Gz*Hz;
        split_kernel<<<(unsigned)((n2 + 255)/256), 256>>>(Wih, p_wih, p_wil, n2);
    }

    // g0ih = x @ Wih0^T + bias0  via bf16-split mma (M=2048, N=2048, ldc=Gz)
    {
        dim3 grid(Gz/128, (Tz*Bz)/128);
        mma_gemm_kernel<<<grid, 256, SMEM_MMA>>>(p_xh, p_xl, p_wih, p_wil, p_b0, p_g0ih, Gz);
    }

    // persistent scan (writes d_out_hi/lo directly)
    scan_kernel<<<NBLK, NTHR>>>(context, Whh, Wih);

    // logits = outs @ Wc^T + bc  via bf16-split mma (ldc=Vz)
    {
        dim3 grid(Vz/128, (Bz*Tz)/128);
        mma_gemm_kernel<<<grid, 256, SMEM_MMA>>>(p_oh, p_ol, p_wch, p_wcl, bc, out, Vz);
    }

    if ((long long)out_size >= (long long)Bz*Tz*Vz + 4LL*Bz*Hz) {
        tail_kernel<<<(4*Bz*Hz + 255)/256, 256>>>(out);
    }
}

// round 10
// speedup vs baseline: 1.5311x; 1.1156x over previous
#include <cuda_runtime.h>
#include <cuda_bf16.h>
#include <math.h>
#include <stdint.h>

#define Bz 32
#define Tz 64
#define Sz 128
#define Hz 512
#define Vz 32000
#define Gz 2048   // 4*H
#define NBLK 128
#define NTHR 256

// ---------------- device scratch ----------------
__device__ __align__(16) float d_x[Tz*Bz*Hz];
__device__ __align__(16) float d_g0ih[Tz*Bz*Gz];
__device__ __align__(16) float d_h0buf[2*Bz*Hz];
__device__ __align__(16) float d_h1buf[2*Bz*Hz];
__device__ __align__(16) float d_cstate[2*Bz*Hz];
__device__ __align__(16) float d_cat1[Bz*Hz];
__device__ __align__(16) float d_attq[Bz*Hz];
__device__ float d_bias0[Gz];
__device__ float d_bias1[Gz];
__device__ unsigned d_bar_cnt;
// bf16 hi/lo splits
__device__ __align__(16) __nv_bfloat16 d_Wc_hi[(size_t)Vz*Hz];
__device__ __align__(16) __nv_bfloat16 d_Wc_lo[(size_t)Vz*Hz];
__device__ __align__(16) __nv_bfloat16 d_out_hi[Bz*Tz*Hz];
__device__ __align__(16) __nv_bfloat16 d_out_lo[Bz*Tz*Hz];
__device__ __align__(16) __nv_bfloat16 d_x_hi[Tz*Bz*Hz];
__device__ __align__(16) __nv_bfloat16 d_x_lo[Tz*Bz*Hz];
__device__ __align__(16) __nv_bfloat16 d_Wih0_hi[Gz*Hz];
__device__ __align__(16) __nv_bfloat16 d_Wih0_lo[Gz*Hz];

__device__ __forceinline__ float sigf(float x) { return 1.f / (1.f + expf(-x)); }

// ---------------- packed f32x2 helpers ----------------
__device__ __forceinline__ void ffma2(unsigned long long &d,
                                      unsigned long long a,
                                      unsigned long long b)
{
    asm("fma.rn.f32x2 %0, %1, %2, %0;" : "+l"(d) : "l"(a), "l"(b));
}
__device__ __forceinline__ float2 unpack2(unsigned long long v)
{
    unsigned lo, hi;
    asm("mov.b64 {%0, %1}, %2;" : "=r"(lo), "=r"(hi) : "l"(v));
    return make_float2(__uint_as_float(lo), __uint_as_float(hi));
}

// ---------------- mma.sync / ldmatrix / cp.async helpers ----------------
__device__ __forceinline__ uint32_t smem_u32(const void* p) {
    uint32_t a;
    asm("{ .reg .u64 t; cvta.to.shared.u64 t, %1; cvt.u32.u64 %0, t; }" : "=r"(a) : "l"(p));
    return a;
}
__device__ __forceinline__ void ldsm4(uint32_t (&r)[4], uint32_t addr)
{
    asm volatile("ldmatrix.sync.aligned.m8n8.x4.shared.b16 {%0,%1,%2,%3}, [%4];"
                 : "=r"(r[0]), "=r"(r[1]), "=r"(r[2]), "=r"(r[3]) : "r"(addr));
}
__device__ __forceinline__ void mma_bf16(float (&c)[4], const uint32_t (&a)[4],
                                         const uint32_t* b)
{
    asm volatile(
        "mma.sync.aligned.m16n8k16.row.col.f32.bf16.bf16.f32 "
        "{%0,%1,%2,%3}, {%4,%5,%6,%7}, {%8,%9}, {%0,%1,%2,%3};"
        : "+f"(c[0]), "+f"(c[1]), "+f"(c[2]), "+f"(c[3])
        : "r"(a[0]), "r"(a[1]), "r"(a[2]), "r"(a[3]), "r"(b[0]), "r"(b[1]));
}
#define CP_ASYNC16(dst, src) \
    asm volatile("cp.async.ca.shared.global [%0], [%1], 16;" :: "r"(dst), "l"(src))
#define CP_ASYNC16_CG(dst, src) \
    asm volatile("cp.async.cg.shared.global [%0], [%1], 16;" :: "r"(dst), "l"(src))
#define CP_COMMIT() asm volatile("cp.async.commit_group;" ::: "memory")
#define CP_WAIT(n)  asm volatile("cp.async.wait_group %0;" :: "n"(n) : "memory")

// ---------------- grid barrier (tight spin, writer fence only) ----------------
__device__ __forceinline__ void gbar(unsigned &nbar)
{
    nbar++;
    __syncthreads();
    if (threadIdx.x == 0) {
        __threadfence();
        atomicAdd(&d_bar_cnt, 1u);
        unsigned target = nbar * (unsigned)NBLK;
        while (*(volatile unsigned*)&d_bar_cnt < target) { }
    }
    __syncthreads();
}

__global__ void reset_kernel() { d_bar_cnt = 0u; }

// ---------------- prep ----------------
__global__ void prep_kernel(const float* __restrict__ bih, const float* __restrict__ bhh,
                            const float* __restrict__ h0, const float* __restrict__ c0)
{
    int i = blockIdx.x * blockDim.x + threadIdx.x;
    if (i < Gz) {
        d_bias0[i] = bih[i] + bhh[i];
        d_bias1[i] = bih[Gz + i] + bhh[Gz + i];
    }
    if (i < Bz*Hz) {
        d_h0buf[i] = h0[i];
        d_h1buf[i] = h0[Bz*Hz + i];
    }
    if (i < 2*Bz*Hz) d_cstate[i] = c0[i];
}

// ---------------- hi/lo bf16 split (vectorized: 4 elems/thread) --------------
__global__ void split_kernel(const float4* __restrict__ src,
                             uint2* __restrict__ hi,
                             uint2* __restrict__ lo, size_t n4)
{
    size_t i = (size_t)blockIdx.x * blockDim.x + threadIdx.x;
    if (i >= n4) return;
    float4 v = src[i];
    __nv_bfloat16 hx = __float2bfloat16(v.x);
    __nv_bfloat16 hy = __float2bfloat16(v.y);
    __nv_bfloat16 hz = __float2bfloat16(v.z);
    __nv_bfloat16 hw = __float2bfloat16(v.w);
    __nv_bfloat16 lx = __float2bfloat16(v.x - __bfloat162float(hx));
    __nv_bfloat16 ly = __float2bfloat16(v.y - __bfloat162float(hy));
    __nv_bfloat16 lz = __float2bfloat16(v.z - __bfloat162float(hz));
    __nv_bfloat16 lw = __float2bfloat16(v.w - __bfloat162float(hw));
    uint2 ho, lu;
    ho.x = (uint32_t)__bfloat16_as_ushort(hx) | ((uint32_t)__bfloat16_as_ushort(hy) << 16);
    ho.y = (uint32_t)__bfloat16_as_ushort(hz) | ((uint32_t)__bfloat16_as_ushort(hw) << 16);
    lu.x = (uint32_t)__bfloat16_as_ushort(lx) | ((uint32_t)__bfloat16_as_ushort(ly) << 16);
    lu.y = (uint32_t)__bfloat16_as_ushort(lz) | ((uint32_t)__bfloat16_as_ushort(lw) << 16);
    hi[i] = ho;
    lo[i] = lu;
}

// ---------------- embedding ----------------
__global__ void embed_kernel(const int* __restrict__ ids32, const float* __restrict__ emb)
{
    int i = blockIdx.x * blockDim.x + threadIdx.x;
    if (i >= Tz*Bz*Hz) return;
    bool is64 = (ids32[1] == 0) && (ids32[3] == 0) && (ids32[5] == 0);
    int h = i % Hz;
    int tb = i / Hz;
    int b = tb % Bz;
    int t = tb / Bz;
    int idx = b*Tz + t;
    int id = is64 ? ids32[2*idx] : ids32[idx];
    if (id < 0 || id >= Vz) id = 0;
    float v = (id == 0) ? 0.f : emb[(size_t)id*Hz + h];
    d_x[i] = v;
    __nv_bfloat16 hv = __float2bfloat16(v);
    d_x_hi[i] = hv;
    d_x_lo[i] = __float2bfloat16(v - __bfloat162float(hv));
}

// ---------------- bf16-split mma GEMM: C[M,N] = A @ B^T + bias ---------------
// C = Ah*Bh + Ah*Bl + Al*Bh. 128x128 CTA tile, 8 warps (2m x 4n),
// K chunks of 32 halves, cp.async double-buffered. 2 CTAs/SM.
#define KC    32
#define KCP   40                         // padded stride (halves)
#define ARRB  (128*KCP*2)                // bytes per array per stage = 10240
#define BUFB  (4*ARRB)                   // bytes per stage buffer = 40960

__global__ void __launch_bounds__(256, 2)
mma_gemm_kernel(const __nv_bfloat16* __restrict__ Ahi, const __nv_bfloat16* __restrict__ Alo,
                const __nv_bfloat16* __restrict__ Bhi, const __nv_bfloat16* __restrict__ Blo,
                const float* __restrict__ bias, float* __restrict__ C, int ldc)
{
    extern __shared__ __align__(16) char sm_raw[];

    const int tid  = threadIdx.x;
    const int lane = tid & 31;
    const int wid  = tid >> 5;
    const int wm   = wid >> 2;
    const int wn   = wid & 3;
    const int n0   = blockIdx.x * 128;
    const int m0   = blockIdx.y * 128;

    float acc[4][4][4];
#pragma unroll
    for (int i = 0; i < 4; ++i)
#pragma unroll
        for (int j = 0; j < 4; ++j)
#pragma unroll
            for (int v = 0; v < 4; ++v) acc[i][j][v] = 0.f;

    const int gr = tid >> 1;           // staged row
    const int gs = (tid & 1) * 2;      // first of 2 segments (8 halves each)

    const uint32_t smBase = smem_u32(sm_raw);

    auto stage = [&](int c, int buf) {
        const int k0 = c * KC;
        uint32_t db = smBase + buf*BUFB + gr*(KCP*2) + gs*16;
        const __nv_bfloat16* pAh = Ahi + (size_t)(m0 + gr)*Hz + k0 + gs*8;
        const __nv_bfloat16* pAl = Alo + (size_t)(m0 + gr)*Hz + k0 + gs*8;
        const __nv_bfloat16* pBh = Bhi + (size_t)(n0 + gr)*Hz + k0 + gs*8;
        const __nv_bfloat16* pBl = Blo + (size_t)(n0 + gr)*Hz + k0 + gs*8;
#pragma unroll
        for (int i = 0; i < 2; ++i) {
            CP_ASYNC16(db + i*16 + 0*ARRB, pAh + i*8);
            CP_ASYNC16(db + i*16 + 1*ARRB, pAl + i*8);
            CP_ASYNC16(db + i*16 + 2*ARRB, pBh + i*8);
            CP_ASYNC16(db + i*16 + 3*ARRB, pBl + i*8);
        }
        CP_COMMIT();
    };

    const int NCHUNK = Hz / KC;   // 16
    stage(0, 0);

    for (int c = 0; c < NCHUNK; ++c) {
        if (c + 1 < NCHUNK) { stage(c + 1, (c + 1) & 1); CP_WAIT(1); }
        else                { CP_WAIT(0); }
        __syncthreads();

        const uint32_t bb  = smBase + (c & 1)*BUFB;
        const uint32_t uAh = bb;
        const uint32_t uAl = bb + 1*ARRB;
        const uint32_t uBh = bb + 2*ARRB;
        const uint32_t uBl = bb + 3*ARRB;

#pragma unroll
        for (int ks = 0; ks < KC/16; ++ks) {
            uint32_t fAh[4][4], fAl[4][4], fBh[4][2], fBl[4][2];
            const int arow = wm*64 + (lane & 15);
            const int acol = ks*16 + ((lane >> 4) << 3);
#pragma unroll
            for (int mt = 0; mt < 4; ++mt) {
                uint32_t off = ((arow + mt*16)*KCP + acol) * 2;
                ldsm4(fAh[mt], uAh + off);
                ldsm4(fAl[mt], uAl + off);
            }
            const int brow = wn*32 + (lane & 7) + ((lane >> 4) << 3);
            const int bcol = ks*16 + (lane & 8);
#pragma unroll
            for (int p = 0; p < 2; ++p) {
                uint32_t off = ((brow + p*16)*KCP + bcol) * 2;
                uint32_t t4[4];
                ldsm4(t4, uBh + off);
                fBh[2*p][0] = t4[0]; fBh[2*p][1] = t4[1];
                fBh[2*p+1][0] = t4[2]; fBh[2*p+1][1] = t4[3];
                ldsm4(t4, uBl + off);
                fBl[2*p][0] = t4[0]; fBl[2*p][1] = t4[1];
                fBl[2*p+1][0] = t4[2]; fBl[2*p+1][1] = t4[3];
            }
#pragma unroll
            for (int mt = 0; mt < 4; ++mt)
#pragma unroll
                for (int nt = 0; nt < 4; ++nt) mma_bf16(acc[mt][nt], fAh[mt], fBh[nt]);
#pragma unroll
            for (int mt = 0; mt < 4; ++mt)
#pragma unroll
                for (int nt = 0; nt < 4; ++nt) mma_bf16(acc[mt][nt], fAh[mt], fBl[nt]);
#pragma unroll
            for (int mt = 0; mt < 4; ++mt)
#pragma unroll
                for (int nt = 0; nt < 4; ++nt) mma_bf16(acc[mt][nt], fAl[mt], fBh[nt]);
        }
        __syncthreads();
    }

    const int gid = lane >> 2;
    const int tig = lane & 3;
#pragma unroll
    for (int mt = 0; mt < 4; ++mt) {
        int mA = m0 + wm*64 + mt*16 + gid;
#pragma unroll
        for (int nt = 0; nt < 4; ++nt) {
            int n = n0 + wn*32 + nt*8 + tig*2;
            float2 bv = *(const float2*)&bias[n];
            float2 v0 = make_float2(acc[mt][nt][0] + bv.x, acc[mt][nt][1] + bv.y);
            float2 v1 = make_float2(acc[mt][nt][2] + bv.x, acc[mt][nt][3] + bv.y);
            *(float2*)&C[(size_t)mA*ldc + n]     = v0;
            *(float2*)&C[(size_t)(mA+8)*ldc + n] = v1;
        }
    }
}

// ---------------- persistent scan (cp.async-pipelined staging) ---------------
// dynamic smem layout
#define SC_HB     0                        // 2 x 32768 B staging buffers
#define SC_SG     65536                    // 16*33*4 = 2112
#define SC_ATTQ   (SC_SG + 2112)           // 2048
#define SC_SC     (SC_ATTQ + 2048)         // 512
#define SC_PART   (SC_SC + 512)            // 1024
#define SC_LSE    (SC_PART + 1024)         // 4
#define SC_TOTAL  (SC_LSE + 16)

__global__ void __launch_bounds__(NTHR, 1)
scan_kernel(const float* __restrict__ ctx, const float* __restrict__ Whh,
            const float* __restrict__ Wih)
{
    extern __shared__ __align__(16) char dynsm[];
    float*  sgp    = (float*)(dynsm + SC_SG);
    float*  attq_s = (float*)(dynsm + SC_ATTQ);
    float*  sc_s   = (float*)(dynsm + SC_SC);
    float*  s_part = (float*)(dynsm + SC_PART);
    float*  s_lse  = (float*)(dynsm + SC_LSE);
    const uint32_t smHb = smem_u32(dynsm);

    const int tid  = threadIdx.x;
    const int lane = tid & 31;
    const int w    = tid >> 5;
    const int blk  = blockIdx.x;
    const int j0   = blk * 4;
    const int cb   = blk >> 2;
    const int cq   = blk & 3;

    const int lr0 = 2*w, lr1 = 2*w + 1;
    const int n0 = (lr0 >> 2)*Hz + j0 + (lr0 & 3);
    const int n1 = (lr1 >> 2)*Hz + j0 + (lr1 & 3);

    ulonglong2 wA0[4], wA1[4], wB0[8], wB1[8];
    {
        const ulonglong2* W0 = (const ulonglong2*)(Whh + (size_t)n0*Hz);
        const ulonglong2* W1 = (const ulonglong2*)(Whh + (size_t)n1*Hz);
#pragma unroll
        for (int i = 0; i < 4; ++i) { wA0[i] = W0[lane + 32*i]; wA1[i] = W1[lane + 32*i]; }
        const ulonglong2* I0 = (const ulonglong2*)(Wih + (size_t)(Gz + n0)*Hz);
        const ulonglong2* I1 = (const ulonglong2*)(Wih + (size_t)(Gz + n1)*Hz);
        const ulonglong2* H0 = (const ulonglong2*)(Whh + (size_t)(Gz + n0)*Hz);
        const ulonglong2* H1 = (const ulonglong2*)(Whh + (size_t)(Gz + n1)*Hz);
#pragma unroll
        for (int i = 0; i < 4; ++i) {
            wB0[i]   = I0[lane + 32*i];  wB1[i]   = I1[lane + 32*i];
            wB0[4+i] = H0[lane + 32*i];  wB1[4+i] = H1[lane + 32*i];
        }
    }

    // stage 32KB chunk (2048 float4) via cp.async.cg (L2-direct: stcg producers)
    auto stageH = [&](const float4* src, int buf) {
        uint32_t db = smHb + buf*32768 + tid*16;
#pragma unroll
        for (int i = 0; i < 8; ++i)
            CP_ASYNC16_CG(db + i*NTHR*16, src + tid + i*NTHR);
        CP_COMMIT();
    };

    // gate GEMV over one staged chunk (16 batches), writes sg rows
    auto gates16 = [&](int buf, int boff, const ulonglong2* wr0, const ulonglong2* wr1, bool add) {
        const ulonglong2* hb2 = (const ulonglong2*)(dynsm + buf*32768);
#pragma unroll 2
        for (int bl = 0; bl < 16; ++bl) {
            unsigned long long a0 = 0ull, a1 = 0ull;
            const ulonglong2* hr = hb2 + bl*128;
#pragma unroll
            for (int i = 0; i < 4; ++i) {
                ulonglong2 h2 = hr[lane + 32*i];
                ffma2(a0, h2.x, wr0[i].x); ffma2(a0, h2.y, wr0[i].y);
                ffma2(a1, h2.x, wr1[i].x); ffma2(a1, h2.y, wr1[i].y);
            }
            float2 f0 = unpack2(a0), f1 = unpack2(a1);
            float s0 = f0.x + f0.y, s1 = f1.x + f1.y;
#pragma unroll
            for (int o = 16; o; o >>= 1) {
                s0 += __shfl_xor_sync(0xffffffffu, s0, o);
                s1 += __shfl_xor_sync(0xffffffffu, s1, o);
            }
            if (lane == 0) {
                int b = boff + bl;
                if (add) { sgp[lr0*33 + b] += s0; sgp[lr1*33 + b] += s1; }
                else     { sgp[lr0*33 + b]  = s0; sgp[lr1*33 + b]  = s1; }
            }
        }
    };

    unsigned nbar = 0;

    for (int t = 0; t < Tz; ++t) {
        const int p = t & 1;
        const float* h0p = d_h0buf + p*Bz*Hz;
        float*       h0n = d_h0buf + (p^1)*Bz*Hz;
        const float* h1p = d_h1buf + p*Bz*Hz;
        float*       h1n = d_h1buf + (p^1)*Bz*Hz;

        // ===== Phase A: layer0 gates (2 chunks, both prefetched) =====
        {
            const float4* Hp = (const float4*)h0p;
            stageH(Hp, 0);
            stageH(Hp + 2048, 1);
            CP_WAIT(1); __syncthreads();
            gates16(0, 0, wA0, wA1, false);
            CP_WAIT(0); __syncthreads();
            gates16(1, 16, wA0, wA1, false);
            __syncthreads();
            if (tid < 128) {
                int b = tid >> 2, jj = tid & 3;
                int j = j0 + jj;
                const float* seed = d_g0ih + ((size_t)t*Bz + b)*Gz;
                float gi = sgp[(0  + jj)*33 + b] + seed[j];
                float gf = sgp[(4  + jj)*33 + b] + seed[Hz + j];
                float gg = sgp[(8  + jj)*33 + b] + seed[2*Hz + j];
                float go = sgp[(12 + jj)*33 + b] + seed[3*Hz + j];
                int ci = b*Hz + j;
                float c = sigf(gf)*d_cstate[ci] + sigf(gi)*tanhf(gg);
                float h = sigf(go)*tanhf(c);
                d_cstate[ci] = c;
                __stcg(&h0n[ci], h);
                __stcg(&d_cat1[ci], h + d_x[((size_t)t*Bz + b)*Hz + j]);
            }
        }
        gbar(nbar);

        // ===== Phase B: layer1 gates, 4 pipelined rounds =====
        // round r: src = (r<2 ? cat1 : h1p) chunk (r&1); weights half = r>>1
        {
            const float4* srcs[4] = { (const float4*)d_cat1, (const float4*)d_cat1 + 2048,
                                      (const float4*)h1p,    (const float4*)h1p + 2048 };
            stageH(srcs[0], 0);
            stageH(srcs[1], 1);
#pragma unroll
            for (int r = 0; r < 4; ++r) {
                CP_WAIT(1); __syncthreads();
                const ulonglong2* wr0 = (r < 2) ? wB0 : (wB0 + 4);
                const ulonglong2* wr1 = (r < 2) ? wB1 : (wB1 + 4);
                gates16(r & 1, (r & 1)*16, wr0, wr1, r >= 2);
                __syncthreads();
                if (r + 2 < 4) stageH(srcs[r + 2], r & 1);
                else if (r == 2) { /* last round handled by wait(1)->wait(0) path */ }
                if (r == 2) { CP_WAIT(0); }   // ensure final group done before r=3 wait
            }
            __syncthreads();
            if (tid < 128) {
                int b = tid >> 2, jj = tid & 3;
                int j = j0 + jj;
                float gi = sgp[(0  + jj)*33 + b] + d_bias1[j];
                float gf = sgp[(4  + jj)*33 + b] + d_bias1[Hz + j];
                float gg = sgp[(8  + jj)*33 + b] + d_bias1[2*Hz + j];
                float go = sgp[(12 + jj)*33 + b] + d_bias1[3*Hz + j];
                int ci = Bz*Hz + b*Hz + j;
                float c = sigf(gf)*d_cstate[ci] + sigf(gi)*tanhf(gg);
                float h = sigf(go)*tanhf(c);
                d_cstate[ci] = c;
                __stcg(&h1n[b*Hz + j], h);
                __stcg(&d_attq[b*Hz + j], h + __ldcg(&d_cat1[b*Hz + j]));
            }
        }
        gbar(nbar);

        // ===== Phase C: attention =====
        {
            for (int i = tid; i < Hz; i += NTHR) attq_s[i] = __ldcg(&d_attq[cb*Hz + i]);
            __syncthreads();

            const float4* A4 = (const float4*)attq_s;
            for (int s = w*16; s < w*16 + 16; ++s) {
                const float4* C4 = (const float4*)(ctx + ((size_t)cb*Sz + s)*Hz);
                float acc = 0.f;
#pragma unroll
                for (int i = 0; i < 4; ++i) {
                    float4 c4 = C4[lane + 32*i];
                    float4 a4 = A4[lane + 32*i];
                    acc += c4.x*a4.x + c4.y*a4.y + c4.z*a4.z + c4.w*a4.w;
                }
#pragma unroll
                for (int o = 16; o; o >>= 1) acc += __shfl_xor_sync(0xffffffffu, acc, o);
                if (lane == 0) sc_s[s] = acc;
            }
            __syncthreads();

            if (w == 0) {
                float m = -1e30f;
                for (int s = lane; s < Sz; s += 32) m = fmaxf(m, sc_s[s]);
#pragma unroll
                for (int o = 16; o; o >>= 1) m = fmaxf(m, __shfl_xor_sync(0xffffffffu, m, o));
                float sm = 0.f;
                for (int s = lane; s < Sz; s += 32) sm += expf(sc_s[s] - m);
#pragma unroll
                for (int o = 16; o; o >>= 1) sm += __shfl_xor_sync(0xffffffffu, sm, o);
                if (lane == 0) *s_lse = m + logf(sm);
            }
            __syncthreads();
            float lse = *s_lse;

            int h = cq*128 + (tid & 127);
            int sgrp = tid >> 7;
            float acc = 0.f;
            for (int s = sgrp*64; s < sgrp*64 + 64; ++s)
                acc += ctx[((size_t)cb*Sz + s)*Hz + h] * (sc_s[s] - lse);
            s_part[tid] = acc;
            __syncthreads();
            if (tid < 128) {
                float v = s_part[tid] + s_part[tid + 128];
                size_t oi = ((size_t)cb*Tz + t)*Hz + h;
                __nv_bfloat16 hv = __float2bfloat16(v);
                d_out_hi[oi] = hv;
                d_out_lo[oi] = __float2bfloat16(v - __bfloat162float(hv));
            }
            __syncthreads();
        }
    }
}

// ---------------- tail: hT, cT ----------------
__global__ void tail_kernel(float* __restrict__ out)
{
    int i = blockIdx.x * blockDim.x + threadIdx.x;
    const size_t base = (size_t)Bz*Tz*Vz;
    if (i < Bz*Hz)                 out[base + i] = d_h0buf[i];
    else if (i < 2*Bz*Hz)          out[base + i] = d_h1buf[i - Bz*Hz];
    else if (i < 4*Bz*Hz)          out[base + i] = d_cstate[i - 2*Bz*Hz];
}

// ---------------- launch ----------------
extern "C" void kernel_launch(void* const* d_in, const int* in_sizes, int n_in,
                              void* d_out, int out_size)
{
    const float* context = (const float*)d_in[0];
    const int*   dec     = (const int*)d_in[1];
    const float* h0      = (const float*)d_in[2];
    const float* c0      = (const float*)d_in[3];
    const float* emb     = (const float*)d_in[4];
    const float* Wih     = (const float*)d_in[5];
    const float* Whh     = (const float*)d_in[6];
    const float* bih     = (const float*)d_in[7];
    const float* bhh     = (const float*)d_in[8];
    const float* Wc      = (const float*)d_in[9];
    const float* bc      = (const float*)d_in[10];
    float* out = (float*)d_out;

    float *p_x, *p_g0ih, *p_b0;
    __nv_bfloat16 *p_wch, *p_wcl, *p_oh, *p_ol, *p_xh, *p_xl, *p_wih, *p_wil;
    cudaGetSymbolAddress((void**)&p_x,    d_x);
    cudaGetSymbolAddress((void**)&p_g0ih, d_g0ih);
    cudaGetSymbolAddress((void**)&p_b0,   d_bias0);
    cudaGetSymbolAddress((void**)&p_wch,  d_Wc_hi);
    cudaGetSymbolAddress((void**)&p_wcl,  d_Wc_lo);
    cudaGetSymbolAddress((void**)&p_oh,   d_out_hi);
    cudaGetSymbolAddress((void**)&p_ol,   d_out_lo);
    cudaGetSymbolAddress((void**)&p_xh,   d_x_hi);
    cudaGetSymbolAddress((void**)&p_xl,   d_x_lo);
    cudaGetSymbolAddress((void**)&p_wih,  d_Wih0_hi);
    cudaGetSymbolAddress((void**)&p_wil,  d_Wih0_lo);

    const int SMEM_MMA = 2 * BUFB;   // 81920 bytes -> 2 CTAs/SM
    cudaFuncSetAttribute(mma_gemm_kernel,
                         cudaFuncAttributeMaxDynamicSharedMemorySize, SMEM_MMA);
    cudaFuncSetAttribute(scan_kernel,
                         cudaFuncAttributeMaxDynamicSharedMemorySize, SC_TOTAL);

    reset_kernel<<<1, 1>>>();
    prep_kernel<<<(2*Bz*Hz + 255)/256, 256>>>(bih, bhh, h0, c0);
    embed_kernel<<<(Tz*Bz*Hz + 255)/256, 256>>>(dec, emb);

    // splits: Wc, Wih layer0 (vectorized)
    {
        size_t n4 = (size_t)Vz*Hz/4;
        split_kernel<<<(unsigned)((n4 + 255)/256), 256>>>((const float4*)Wc, (uint2*)p_wch, (uint2*)p_wcl, n4);
        size_t m4 = (size_t)Gz*Hz/4;
        split_kernel<<<(unsigned)((m4 + 255)/256), 256>>>((const float4*)Wih, (uint2*)p_wih, (uint2*)p_wil, m4);
    }

    // g0ih = x @ Wih0^T + bias0
    {
        dim3 grid(Gz/128, (Tz*Bz)/128);
        mma_gemm_kernel<<<grid, 256, SMEM_MMA>>>(p_xh, p_xl, p_wih, p_wil, p_b0, p_g0ih, Gz);
    }

    // persistent scan (writes d_out_hi/lo directly)
    scan_kernel<<<NBLK, NTHR, SC_TOTAL>>>(context, Whh, Wih);

    // logits = outs @ Wc^T + bc
    {
        dim3 grid(Vz/128, (Bz*Tz)/128);
        mma_gemm_kernel<<<grid, 256, SMEM_MMA>>>(p_oh, p_ol, p_wch, p_wcl, bc, out, Vz);
    }

    if ((long long)out_size >= (long long)Bz*Tz*Vz + 4LL*Bz*Hz) {
        tail_kernel<<<(4*Bz*Hz + 255)/256, 256>>>(out);
    }
}

// round 11
// speedup vs baseline: 1.6400x; 1.0711x over previous
#include <cuda_runtime.h>
#include <cuda_bf16.h>
#include <math.h>
#include <stdint.h>

#define Bz 32
#define Tz 64
#define Sz 128
#define Hz 512
#define Vz 32000
#define Gz 2048   // 4*H
#define NBLK 128
#define NTHR 256

// ---------------- device scratch ----------------
__device__ __align__(16) float d_x[Tz*Bz*Hz];
__device__ __align__(16) float d_g0ih[Tz*Bz*Gz];
__device__ __align__(16) float d_h0buf[2*Bz*Hz];
__device__ __align__(16) float d_h1buf[2*Bz*Hz];
__device__ __align__(16) float d_cstate[2*Bz*Hz];
__device__ __align__(16) float d_cat1[Bz*Hz];
__device__ __align__(16) float d_attq[Bz*Hz];
__device__ float d_bias0[Gz];
__device__ float d_bias1[Gz];
__device__ unsigned d_bar_cnt;
// bf16 hi/lo splits
__device__ __align__(16) __nv_bfloat16 d_Wc_hi[(size_t)Vz*Hz];
__device__ __align__(16) __nv_bfloat16 d_Wc_lo[(size_t)Vz*Hz];
__device__ __align__(16) __nv_bfloat16 d_out_hi[Bz*Tz*Hz];
__device__ __align__(16) __nv_bfloat16 d_out_lo[Bz*Tz*Hz];
__device__ __align__(16) __nv_bfloat16 d_x_hi[Tz*Bz*Hz];
__device__ __align__(16) __nv_bfloat16 d_x_lo[Tz*Bz*Hz];
__device__ __align__(16) __nv_bfloat16 d_Wih0_hi[Gz*Hz];
__device__ __align__(16) __nv_bfloat16 d_Wih0_lo[Gz*Hz];

__device__ __forceinline__ float sigf(float x) { return 1.f / (1.f + expf(-x)); }

// ---------------- packed f32x2 helpers ----------------
__device__ __forceinline__ void ffma2(unsigned long long &d,
                                      unsigned long long a,
                                      unsigned long long b)
{
    asm("fma.rn.f32x2 %0, %1, %2, %0;" : "+l"(d) : "l"(a), "l"(b));
}
__device__ __forceinline__ float2 unpack2(unsigned long long v)
{
    unsigned lo, hi;
    asm("mov.b64 {%0, %1}, %2;" : "=r"(lo), "=r"(hi) : "l"(v));
    return make_float2(__uint_as_float(lo), __uint_as_float(hi));
}

// ---------------- mma.sync / ldmatrix / cp.async helpers ----------------
__device__ __forceinline__ uint32_t smem_u32(const void* p) {
    uint32_t a;
    asm("{ .reg .u64 t; cvta.to.shared.u64 t, %1; cvt.u32.u64 %0, t; }" : "=r"(a) : "l"(p));
    return a;
}
__device__ __forceinline__ void ldsm4(uint32_t (&r)[4], uint32_t addr)
{
    asm volatile("ldmatrix.sync.aligned.m8n8.x4.shared.b16 {%0,%1,%2,%3}, [%4];"
                 : "=r"(r[0]), "=r"(r[1]), "=r"(r[2]), "=r"(r[3]) : "r"(addr));
}
__device__ __forceinline__ void mma_bf16(float (&c)[4], const uint32_t (&a)[4],
                                         const uint32_t* b)
{
    asm volatile(
        "mma.sync.aligned.m16n8k16.row.col.f32.bf16.bf16.f32 "
        "{%0,%1,%2,%3}, {%4,%5,%6,%7}, {%8,%9}, {%0,%1,%2,%3};"
        : "+f"(c[0]), "+f"(c[1]), "+f"(c[2]), "+f"(c[3])
        : "r"(a[0]), "r"(a[1]), "r"(a[2]), "r"(a[3]), "r"(b[0]), "r"(b[1]));
}
#define CP_ASYNC16_CG(dst, src) \
    asm volatile("cp.async.cg.shared.global [%0], [%1], 16;" :: "r"(dst), "l"(src))
#define CP_COMMIT() asm volatile("cp.async.commit_group;" ::: "memory")
#define CP_WAIT(n)  asm volatile("cp.async.wait_group %0;" :: "n"(n) : "memory")

// ---------------- grid barrier ----------------
__device__ __forceinline__ void gbar(unsigned &nbar)
{
    nbar++;
    __syncthreads();
    if (threadIdx.x == 0) {
        __threadfence();
        atomicAdd(&d_bar_cnt, 1u);
        unsigned target = nbar * (unsigned)NBLK;
        while (*(volatile unsigned*)&d_bar_cnt < target) { }
    }
    __syncthreads();
}

// ---------------- fused init: barrier reset + prep + embed -------------------
__global__ void init_kernel(const int* __restrict__ ids32, const float* __restrict__ emb,
                            const float* __restrict__ bih, const float* __restrict__ bhh,
                            const float* __restrict__ h0, const float* __restrict__ c0)
{
    int i = blockIdx.x * blockDim.x + threadIdx.x;
    if (i == 0) d_bar_cnt = 0u;
    if (i < Gz) {
        d_bias0[i] = bih[i] + bhh[i];
        d_bias1[i] = bih[Gz + i] + bhh[Gz + i];
    }
    if (i < Bz*Hz) {
        d_h0buf[i] = h0[i];
        d_h1buf[i] = h0[Bz*Hz + i];
    }
    if (i < 2*Bz*Hz) d_cstate[i] = c0[i];
    if (i < Tz*Bz*Hz) {
        bool is64 = (ids32[1] == 0) && (ids32[3] == 0) && (ids32[5] == 0);
        int h = i % Hz;
        int tb = i / Hz;
        int b = tb % Bz;
        int t = tb / Bz;
        int idx = b*Tz + t;
        int id = is64 ? ids32[2*idx] : ids32[idx];
        if (id < 0 || id >= Vz) id = 0;
        float v = (id == 0) ? 0.f : emb[(size_t)id*Hz + h];
        d_x[i] = v;
        __nv_bfloat16 hv = __float2bfloat16(v);
        d_x_hi[i] = hv;
        d_x_lo[i] = __float2bfloat16(v - __bfloat162float(hv));
    }
}

// ---------------- hi/lo bf16 split (vectorized) ----------------
__global__ void split_kernel(const float4* __restrict__ src,
                             uint2* __restrict__ hi,
                             uint2* __restrict__ lo, size_t n4)
{
    size_t i = (size_t)blockIdx.x * blockDim.x + threadIdx.x;
    if (i >= n4) return;
    float4 v = src[i];
    __nv_bfloat16 hx = __float2bfloat16(v.x);
    __nv_bfloat16 hy = __float2bfloat16(v.y);
    __nv_bfloat16 hz = __float2bfloat16(v.z);
    __nv_bfloat16 hw = __float2bfloat16(v.w);
    __nv_bfloat16 lx = __float2bfloat16(v.x - __bfloat162float(hx));
    __nv_bfloat16 ly = __float2bfloat16(v.y - __bfloat162float(hy));
    __nv_bfloat16 lz = __float2bfloat16(v.z - __bfloat162float(hz));
    __nv_bfloat16 lw = __float2bfloat16(v.w - __bfloat162float(hw));
    uint2 ho, lu;
    ho.x = (uint32_t)__bfloat16_as_ushort(hx) | ((uint32_t)__bfloat16_as_ushort(hy) << 16);
    ho.y = (uint32_t)__bfloat16_as_ushort(hz) | ((uint32_t)__bfloat16_as_ushort(hw) << 16);
    lu.x = (uint32_t)__bfloat16_as_ushort(lx) | ((uint32_t)__bfloat16_as_ushort(ly) << 16);
    lu.y = (uint32_t)__bfloat16_as_ushort(lz) | ((uint32_t)__bfloat16_as_ushort(lw) << 16);
    hi[i] = ho;
    lo[i] = lu;
}

// ---------------- bf16-split mma GEMM: C[M,N] = A @ B^T + bias ---------------
#define KC    32
#define KCP   40
#define ARRB  (128*KCP*2)                // 10240
#define BUFB  (4*ARRB)                   // 40960

__global__ void __launch_bounds__(256, 2)
mma_gemm_kernel(const __nv_bfloat16* __restrict__ Ahi, const __nv_bfloat16* __restrict__ Alo,
                const __nv_bfloat16* __restrict__ Bhi, const __nv_bfloat16* __restrict__ Blo,
                const float* __restrict__ bias, float* __restrict__ C, int ldc)
{
    extern __shared__ __align__(16) char sm_raw[];

    const int tid  = threadIdx.x;
    const int lane = tid & 31;
    const int wid  = tid >> 5;
    const int wm   = wid >> 2;
    const int wn   = wid & 3;
    const int n0   = blockIdx.x * 128;
    const int m0   = blockIdx.y * 128;

    float acc[4][4][4];
#pragma unroll
    for (int i = 0; i < 4; ++i)
#pragma unroll
        for (int j = 0; j < 4; ++j)
#pragma unroll
            for (int v = 0; v < 4; ++v) acc[i][j][v] = 0.f;

    const int gr = tid >> 1;
    const int gs = (tid & 1) * 2;

    const uint32_t smBase = smem_u32(sm_raw);

    auto stage = [&](int c, int buf) {
        const int k0 = c * KC;
        uint32_t db = smBase + buf*BUFB + gr*(KCP*2) + gs*16;
        const __nv_bfloat16* pAh = Ahi + (size_t)(m0 + gr)*Hz + k0 + gs*8;
        const __nv_bfloat16* pAl = Alo + (size_t)(m0 + gr)*Hz + k0 + gs*8;
        const __nv_bfloat16* pBh = Bhi + (size_t)(n0 + gr)*Hz + k0 + gs*8;
        const __nv_bfloat16* pBl = Blo + (size_t)(n0 + gr)*Hz + k0 + gs*8;
#pragma unroll
        for (int i = 0; i < 2; ++i) {
            CP_ASYNC16_CG(db + i*16 + 0*ARRB, pAh + i*8);
            CP_ASYNC16_CG(db + i*16 + 1*ARRB, pAl + i*8);
            CP_ASYNC16_CG(db + i*16 + 2*ARRB, pBh + i*8);
            CP_ASYNC16_CG(db + i*16 + 3*ARRB, pBl + i*8);
        }
        CP_COMMIT();
    };

    const int NCHUNK = Hz / KC;   // 16
    stage(0, 0);

    for (int c = 0; c < NCHUNK; ++c) {
        if (c + 1 < NCHUNK) { stage(c + 1, (c + 1) & 1); CP_WAIT(1); }
        else                { CP_WAIT(0); }
        __syncthreads();

        const uint32_t bb  = smBase + (c & 1)*BUFB;
        const uint32_t uAh = bb;
        const uint32_t uAl = bb + 1*ARRB;
        const uint32_t uBh = bb + 2*ARRB;
        const uint32_t uBl = bb + 3*ARRB;

#pragma unroll
        for (int ks = 0; ks < KC/16; ++ks) {
            uint32_t fAh[4][4], fAl[4][4], fBh[4][2], fBl[4][2];
            const int arow = wm*64 + (lane & 15);
            const int acol = ks*16 + ((lane >> 4) << 3);
#pragma unroll
            for (int mt = 0; mt < 4; ++mt) {
                uint32_t off = ((arow + mt*16)*KCP + acol) * 2;
                ldsm4(fAh[mt], uAh + off);
                ldsm4(fAl[mt], uAl + off);
            }
            const int brow = wn*32 + (lane & 7) + ((lane >> 4) << 3);
            const int bcol = ks*16 + (lane & 8);
#pragma unroll
            for (int p = 0; p < 2; ++p) {
                uint32_t off = ((brow + p*16)*KCP + bcol) * 2;
                uint32_t t4[4];
                ldsm4(t4, uBh + off);
                fBh[2*p][0] = t4[0]; fBh[2*p][1] = t4[1];
                fBh[2*p+1][0] = t4[2]; fBh[2*p+1][1] = t4[3];
                ldsm4(t4, uBl + off);
                fBl[2*p][0] = t4[0]; fBl[2*p][1] = t4[1];
                fBl[2*p+1][0] = t4[2]; fBl[2*p+1][1] = t4[3];
            }
#pragma unroll
            for (int mt = 0; mt < 4; ++mt)
#pragma unroll
                for (int nt = 0; nt < 4; ++nt) mma_bf16(acc[mt][nt], fAh[mt], fBh[nt]);
#pragma unroll
            for (int mt = 0; mt < 4; ++mt)
#pragma unroll
                for (int nt = 0; nt < 4; ++nt) mma_bf16(acc[mt][nt], fAh[mt], fBl[nt]);
#pragma unroll
            for (int mt = 0; mt < 4; ++mt)
#pragma unroll
                for (int nt = 0; nt < 4; ++nt) mma_bf16(acc[mt][nt], fAl[mt], fBh[nt]);
        }
        __syncthreads();
    }

    const int gid = lane >> 2;
    const int tig = lane & 3;
#pragma unroll
    for (int mt = 0; mt < 4; ++mt) {
        int mA = m0 + wm*64 + mt*16 + gid;
#pragma unroll
        for (int nt = 0; nt < 4; ++nt) {
            int n = n0 + wn*32 + nt*8 + tig*2;
            float2 bv = *(const float2*)&bias[n];
            float2 v0 = make_float2(acc[mt][nt][0] + bv.x, acc[mt][nt][1] + bv.y);
            float2 v1 = make_float2(acc[mt][nt][2] + bv.x, acc[mt][nt][3] + bv.y);
            *(float2*)&C[(size_t)mA*ldc + n]     = v0;
            *(float2*)&C[(size_t)(mA+8)*ldc + n] = v1;
        }
    }
}

// ---------------- persistent scan ----------------
// dynamic smem layout
#define SC_HB     0                        // 2 x 32768 staging
#define SC_SG     65536                    // 16 rows x 32 b x 16 slots x4B = 32768
#define SC_ATTQ   (SC_SG + 32768)          // 2048
#define SC_SC     (SC_ATTQ + 2048)         // 512
#define SC_LSE    (SC_SC + 512)            // 16
#define SC_TOTAL  (SC_LSE + 16)

__global__ void __launch_bounds__(NTHR, 1)
scan_kernel(const float* __restrict__ ctx, const float* __restrict__ Whh,
            const float* __restrict__ Wih)
{
    extern __shared__ __align__(16) char dynsm[];
    float*  sgp    = (float*)(dynsm + SC_SG);     // [row][b][16 slots]
    float*  attq_s = (float*)(dynsm + SC_ATTQ);
    float*  sc_s   = (float*)(dynsm + SC_SC);
    float*  s_lse  = (float*)(dynsm + SC_LSE);
    const uint32_t smHb = smem_u32(dynsm);

    const int tid  = threadIdx.x;
    const int lane = tid & 31;
    const int w    = tid >> 5;
    const int blk  = blockIdx.x;
    const int j0   = blk * 4;
    // attention assignment: even blocks only; batch = blk>>2, H-half = (blk>>1)&1
    const bool att_on = (blk & 1) == 0;
    const int cb   = blk >> 2;
    const int chalf = (blk >> 1) & 1;

    const int lr0 = 2*w, lr1 = 2*w + 1;
    const int n0 = (lr0 >> 2)*Hz + j0 + (lr0 & 3);
    const int n1 = (lr1 >> 2)*Hz + j0 + (lr1 & 3);

    ulonglong2 wA0[4], wA1[4], wB0[8], wB1[8];
    {
        const ulonglong2* W0 = (const ulonglong2*)(Whh + (size_t)n0*Hz);
        const ulonglong2* W1 = (const ulonglong2*)(Whh + (size_t)n1*Hz);
#pragma unroll
        for (int i = 0; i < 4; ++i) { wA0[i] = W0[lane + 32*i]; wA1[i] = W1[lane + 32*i]; }
        const ulonglong2* I0 = (const ulonglong2*)(Wih + (size_t)(Gz + n0)*Hz);
        const ulonglong2* I1 = (const ulonglong2*)(Wih + (size_t)(Gz + n1)*Hz);
        const ulonglong2* H0 = (const ulonglong2*)(Whh + (size_t)(Gz + n0)*Hz);
        const ulonglong2* H1 = (const ulonglong2*)(Whh + (size_t)(Gz + n1)*Hz);
#pragma unroll
        for (int i = 0; i < 4; ++i) {
            wB0[i]   = I0[lane + 32*i];  wB1[i]   = I1[lane + 32*i];
            wB0[4+i] = H0[lane + 32*i];  wB1[4+i] = H1[lane + 32*i];
        }
    }

    auto stageH = [&](const float4* src, int buf) {
        uint32_t db = smHb + buf*32768 + tid*16;
#pragma unroll
        for (int i = 0; i < 8; ++i)
            CP_ASYNC16_CG(db + i*NTHR*16, src + tid + i*NTHR);
        CP_COMMIT();
    };

    // gate GEMV over staged chunk; 2-level shfl -> 8 partials into sg slots
    auto gates16 = [&](int buf, int boff, int slotbase,
                       const ulonglong2* wr0, const ulonglong2* wr1) {
        const ulonglong2* hb2 = (const ulonglong2*)(dynsm + buf*32768);
#pragma unroll 2
        for (int bl = 0; bl < 16; ++bl) {
            unsigned long long a0 = 0ull, a1 = 0ull;
            const ulonglong2* hr = hb2 + bl*128;
#pragma unroll
            for (int i = 0; i < 4; ++i) {
                ulonglong2 h2 = hr[lane + 32*i];
                ffma2(a0, h2.x, wr0[i].x); ffma2(a0, h2.y, wr0[i].y);
                ffma2(a1, h2.x, wr1[i].x); ffma2(a1, h2.y, wr1[i].y);
            }
            float2 f0 = unpack2(a0), f1 = unpack2(a1);
            float s0 = f0.x + f0.y, s1 = f1.x + f1.y;
            s0 += __shfl_xor_sync(0xffffffffu, s0, 16);
            s1 += __shfl_xor_sync(0xffffffffu, s1, 16);
            s0 += __shfl_xor_sync(0xffffffffu, s0, 8);
            s1 += __shfl_xor_sync(0xffffffffu, s1, 8);
            if (lane < 8) {
                int b = boff + bl;
                sgp[(lr0*32 + b)*16 + slotbase + lane] = s0;
                sgp[(lr1*32 + b)*16 + slotbase + lane] = s1;
            }
        }
    };

    unsigned nbar = 0;

    for (int t = 0; t < Tz; ++t) {
        const int p = t & 1;
        const float* h0p = d_h0buf + p*Bz*Hz;
        float*       h0n = d_h0buf + (p^1)*Bz*Hz;
        const float* h1p = d_h1buf + p*Bz*Hz;
        float*       h1n = d_h1buf + (p^1)*Bz*Hz;

        // ===== Phase A: layer0 gates =====
        {
            const float4* Hp = (const float4*)h0p;
            stageH(Hp, 0);
            stageH(Hp + 2048, 1);
            CP_WAIT(1); __syncthreads();
            gates16(0, 0, 0, wA0, wA1);
            CP_WAIT(0); __syncthreads();
            gates16(1, 16, 0, wA0, wA1);
            __syncthreads();
            if (tid < 128) {
                int b = tid >> 2, jj = tid & 3;
                int j = j0 + jj;
                const float* seed = d_g0ih + ((size_t)t*Bz + b)*Gz;
                float g4[4];
#pragma unroll
                for (int g = 0; g < 4; ++g) {
                    const float4* q = (const float4*)&sgp[((g*4 + jj)*32 + b)*16];
                    float4 q0 = q[0], q1 = q[1];
                    g4[g] = (q0.x + q0.y) + (q0.z + q0.w) + (q1.x + q1.y) + (q1.z + q1.w);
                }
                float gi = g4[0] + seed[j];
                float gf = g4[1] + seed[Hz + j];
                float gg = g4[2] + seed[2*Hz + j];
                float go = g4[3] + seed[3*Hz + j];
                int ci = b*Hz + j;
                float c = sigf(gf)*d_cstate[ci] + sigf(gi)*tanhf(gg);
                float h = sigf(go)*tanhf(c);
                d_cstate[ci] = c;
                __stcg(&h0n[ci], h);
                __stcg(&d_cat1[ci], h + d_x[((size_t)t*Bz + b)*Hz + j]);
            }
        }
        gbar(nbar);

        // ===== Phase B: layer1 gates, 4 pipelined rounds =====
        {
            const float4* srcs[4] = { (const float4*)d_cat1, (const float4*)d_cat1 + 2048,
                                      (const float4*)h1p,    (const float4*)h1p + 2048 };
            stageH(srcs[0], 0);
            stageH(srcs[1], 1);
#pragma unroll
            for (int r = 0; r < 4; ++r) {
                CP_WAIT(1); __syncthreads();
                const ulonglong2* wr0 = (r < 2) ? wB0 : (wB0 + 4);
                const ulonglong2* wr1 = (r < 2) ? wB1 : (wB1 + 4);
                gates16(r & 1, (r & 1)*16, (r < 2) ? 0 : 8, wr0, wr1);
                __syncthreads();
                if (r + 2 < 4) stageH(srcs[r + 2], r & 1);
                if (r == 2) { CP_WAIT(0); }
            }
            __syncthreads();
            if (tid < 128) {
                int b = tid >> 2, jj = tid & 3;
                int j = j0 + jj;
                float g4[4];
#pragma unroll
                for (int g = 0; g < 4; ++g) {
                    const float4* q = (const float4*)&sgp[((g*4 + jj)*32 + b)*16];
                    float4 q0 = q[0], q1 = q[1], q2 = q[2], q3 = q[3];
                    g4[g] = ((q0.x + q0.y) + (q0.z + q0.w)) + ((q1.x + q1.y) + (q1.z + q1.w))
                          + ((q2.x + q2.y) + (q2.z + q2.w)) + ((q3.x + q3.y) + (q3.z + q3.w));
                }
                float gi = g4[0] + d_bias1[j];
                float gf = g4[1] + d_bias1[Hz + j];
                float gg = g4[2] + d_bias1[2*Hz + j];
                float go = g4[3] + d_bias1[3*Hz + j];
                int ci = Bz*Hz + b*Hz + j;
                float c = sigf(gf)*d_cstate[ci] + sigf(gi)*tanhf(gg);
                float h = sigf(go)*tanhf(c);
                d_cstate[ci] = c;
                __stcg(&h1n[b*Hz + j], h);
                __stcg(&d_attq[b*Hz + j], h + __ldcg(&d_cat1[b*Hz + j]));
            }
        }
        gbar(nbar);

        // ===== Phase C: attention (even blocks only; batch cb, H-half chalf) ====
        if (att_on) {
            for (int i = tid; i < Hz; i += NTHR) attq_s[i] = __ldcg(&d_attq[cb*Hz + i]);
            __syncthreads();

            const float4* A4 = (const float4*)attq_s;
            for (int s = w*16; s < w*16 + 16; ++s) {
                const float4* C4 = (const float4*)(ctx + ((size_t)cb*Sz + s)*Hz);
                float acc = 0.f;
#pragma unroll
                for (int i = 0; i < 4; ++i) {
                    float4 c4 = C4[lane + 32*i];
                    float4 a4 = A4[lane + 32*i];
                    acc += c4.x*a4.x + c4.y*a4.y + c4.z*a4.z + c4.w*a4.w;
                }
#pragma unroll
                for (int o = 16; o; o >>= 1) acc += __shfl_xor_sync(0xffffffffu, acc, o);
                if (lane == 0) sc_s[s] = acc;
            }
            __syncthreads();

            if (w == 0) {
                float m = -1e30f;
                for (int s = lane; s < Sz; s += 32) m = fmaxf(m, sc_s[s]);
#pragma unroll
                for (int o = 16; o; o >>= 1) m = fmaxf(m, __shfl_xor_sync(0xffffffffu, m, o));
                float sm = 0.f;
                for (int s = lane; s < Sz; s += 32) sm += expf(sc_s[s] - m);
#pragma unroll
                for (int o = 16; o; o >>= 1) sm += __shfl_xor_sync(0xffffffffu, sm, o);
                if (lane == 0) *s_lse = m + logf(sm);
            }
            __syncthreads();
            float lse = *s_lse;

            // weighted sum over this block's 256-wide H half
            int h = chalf*256 + tid;
            const float* cp = ctx + (size_t)cb*Sz*Hz + h;
            float acc = 0.f;
#pragma unroll 8
            for (int s = 0; s < Sz; ++s)
                acc += cp[(size_t)s*Hz] * (sc_s[s] - lse);
            size_t oi = ((size_t)cb*Tz + t)*Hz + h;
            __nv_bfloat16 hv = __float2bfloat16(acc);
            d_out_hi[oi] = hv;
            d_out_lo[oi] = __float2bfloat16(acc - __bfloat162float(hv));
            __syncthreads();
        }
    }
}

// ---------------- tail: hT, cT ----------------
__global__ void tail_kernel(float* __restrict__ out)
{
    int i = blockIdx.x * blockDim.x + threadIdx.x;
    const size_t base = (size_t)Bz*Tz*Vz;
    if (i < Bz*Hz)                 out[base + i] = d_h0buf[i];
    else if (i < 2*Bz*Hz)          out[base + i] = d_h1buf[i - Bz*Hz];
    else if (i < 4*Bz*Hz)          out[base + i] = d_cstate[i - 2*Bz*Hz];
}

// ---------------- launch ----------------
extern "C" void kernel_launch(void* const* d_in, const int* in_sizes, int n_in,
                              void* d_out, int out_size)
{
    const float* context = (const float*)d_in[0];
    const int*   dec     = (const int*)d_in[1];
    const float* h0      = (const float*)d_in[2];
    const float* c0      = (const float*)d_in[3];
    const float* emb     = (const float*)d_in[4];
    const float* Wih     = (const float*)d_in[5];
    const float* Whh     = (const float*)d_in[6];
    const float* bih     = (const float*)d_in[7];
    const float* bhh     = (const float*)d_in[8];
    const float* Wc      = (const float*)d_in[9];
    const float* bc      = (const float*)d_in[10];
    float* out = (float*)d_out;

    float *p_g0ih, *p_b0;
    __nv_bfloat16 *p_wch, *p_wcl, *p_oh, *p_ol, *p_xh, *p_xl, *p_wih, *p_wil;
    cudaGetSymbolAddress((void**)&p_g0ih, d_g0ih);
    cudaGetSymbolAddress((void**)&p_b0,   d_bias0);
    cudaGetSymbolAddress((void**)&p_wch,  d_Wc_hi);
    cudaGetSymbolAddress((void**)&p_wcl,  d_Wc_lo);
    cudaGetSymbolAddress((void**)&p_oh,   d_out_hi);
    cudaGetSymbolAddress((void**)&p_ol,   d_out_lo);
    cudaGetSymbolAddress((void**)&p_xh,   d_x_hi);
    cudaGetSymbolAddress((void**)&p_xl,   d_x_lo);
    cudaGetSymbolAddress((void**)&p_wih,  d_Wih0_hi);
    cudaGetSymbolAddress((void**)&p_wil,  d_Wih0_lo);

    const int SMEM_MMA = 2 * BUFB;   // 81920 -> 2 CTAs/SM
    cudaFuncSetAttribute(mma_gemm_kernel,
                         cudaFuncAttributeMaxDynamicSharedMemorySize, SMEM_MMA);
    cudaFuncSetAttribute(scan_kernel,
                         cudaFuncAttributeMaxDynamicSharedMemorySize, SC_TOTAL);

    // fused init (barrier reset + biases + state + embedding + x splits)
    init_kernel<<<(Tz*Bz*Hz + 255)/256, 256>>>(dec, emb, bih, bhh, h0, c0);

    // splits: Wc, Wih layer0
    {
        size_t n4 = (size_t)Vz*Hz/4;
        split_kernel<<<(unsigned)((n4 + 255)/256), 256>>>((const float4*)Wc, (uint2*)p_wch, (uint2*)p_wcl, n4);
        size_t m4 = (size_t)Gz*Hz/4;
        split_kernel<<<(unsigned)((m4 + 255)/256), 256>>>((const float4*)Wih, (uint2*)p_wih, (uint2*)p_wil, m4);
    }

    // g0ih = x @ Wih0^T + bias0
    {
        dim3 grid(Gz/128, (Tz*Bz)/128);
        mma_gemm_kernel<<<grid, 256, SMEM_MMA>>>(p_xh, p_xl, p_wih, p_wil, p_b0, p_g0ih, Gz);
    }

    // persistent scan (writes d_out_hi/lo directly)
    scan_kernel<<<NBLK, NTHR, SC_TOTAL>>>(context, Whh, Wih);

    // logits = outs @ Wc^T + bc
    {
        dim3 grid(Vz/128, (Bz*Tz)/128);
        mma_gemm_kernel<<<grid, 256, SMEM_MMA>>>(p_oh, p_ol, p_wch, p_wcl, bc, out, Vz);
    }

    if ((long long)out_size >= (long long)Bz*Tz*Vz + 4LL*Bz*Hz) {
        tail_kernel<<<(4*Bz*Hz + 255)/256, 256>>>(out);
    }
}